// round 1
// baseline (speedup 1.0000x reference)
#include <cuda_runtime.h>
#include <math.h>

#define BATCH 16
#define IMG 56
#define PP 28
#define NPOS 784
#define DIM 256
#define HEADS 8
#define DH 64
#define INNER 512

// ---------------- scratch (static device allocations; no cudaMalloc) -------
__device__ float g_xpool[BATCH * NPOS * DIM];   // pooled, channel-last [b, p, c]
__device__ float g_attn2[BATCH * NPOS * 2];     // mean/max over channels
__device__ float g_q[BATCH * HEADS * NPOS * 2];
__device__ float g_k[BATCH * HEADS * NPOS * 2];
__device__ float g_vmid[BATCH * NPOS * DIM];    // after dw+BN+GELU
__device__ float g_v[BATCH * NPOS * INNER];     // after pointwise conv [b,p,ch]
__device__ float g_ao[BATCH * NPOS * INNER];    // attention out [b,p,h*64+d]
__device__ float g_y28[BATCH * NPOS * DIM];     // after out-proj [b,p,c]

// bicubic (a=-0.75) weights for t=0.25 and t=0.75 (half-pixel, x2)
__constant__ float c_W25[4] = {-0.10546875f, 0.87890625f, 0.26171875f, -0.03515625f};
__constant__ float c_W75[4] = {-0.03515625f, 0.26171875f, 0.87890625f, -0.10546875f};

// ---------------- 1) avgpool(3,2,1) + channel mean/max ---------------------
__global__ void pool_stats_kernel(const float* __restrict__ x) {
    int p = blockIdx.x, b = blockIdx.y, c = threadIdx.x;
    int py = p / PP, px = p % PP;
    float acc = 0.f;
#pragma unroll
    for (int wy = 0; wy < 3; wy++) {
        int iy = 2 * py - 1 + wy;
        if ((unsigned)iy >= IMG) continue;
#pragma unroll
        for (int wx = 0; wx < 3; wx++) {
            int ix = 2 * px - 1 + wx;
            if ((unsigned)ix >= IMG) continue;
            acc += x[((size_t)b * IMG * IMG + iy * IMG + ix) * DIM + c];
        }
    }
    float pool = acc * (1.f / 9.f);
    g_xpool[((size_t)b * NPOS + p) * DIM + c] = pool;

    float vs = pool, vm = pool;
#pragma unroll
    for (int o = 16; o > 0; o >>= 1) {
        vs += __shfl_down_sync(0xffffffffu, vs, o);
        vm = fmaxf(vm, __shfl_down_sync(0xffffffffu, vm, o));
    }
    __shared__ float ss[8], sm[8];
    int lane = c & 31, w = c >> 5;
    if (lane == 0) { ss[w] = vs; sm[w] = vm; }
    __syncthreads();
    if (c == 0) {
        float S = ss[0], M = sm[0];
#pragma unroll
        for (int i = 1; i < 8; i++) { S += ss[i]; M = fmaxf(M, sm[i]); }
        g_attn2[((size_t)b * NPOS + p) * 2 + 0] = S * (1.f / DIM);
        g_attn2[((size_t)b * NPOS + p) * 2 + 1] = M;
    }
}

// ---------------- 2) q/k 3x3 convs on the 2-channel attention map ----------
__global__ void qk_conv_kernel(const float* __restrict__ qw, const float* __restrict__ qb,
                               const float* __restrict__ kw, const float* __restrict__ kb) {
    int p = blockIdx.x, b = blockIdx.y, t = threadIdx.x;
    int sel = t >> 4, och = t & 15;
    const float* w = sel ? kw : qw;
    const float* bi = sel ? kb : qb;
    float* outp = sel ? g_k : g_q;
    int py = p / PP, px = p % PP;
    float acc = bi[och];
#pragma unroll
    for (int dy = 0; dy < 3; dy++) {
        int iy = py - 1 + dy;
        if ((unsigned)iy >= PP) continue;
#pragma unroll
        for (int dx = 0; dx < 3; dx++) {
            int ix = px - 1 + dx;
            if ((unsigned)ix >= PP) continue;
            const float* a2 = &g_attn2[((size_t)b * NPOS + iy * PP + ix) * 2];
            acc += w[((och * 2 + 0) * 3 + dy) * 3 + dx] * a2[0]
                 + w[((och * 2 + 1) * 3 + dy) * 3 + dx] * a2[1];
        }
    }
    int h = och >> 1, comp = och & 1;
    outp[(((size_t)b * HEADS + h) * NPOS + p) * 2 + comp] = acc;
}

// ---------------- 3) depthwise 3x3 + BN(eval) + exact GELU -----------------
__global__ void dw_bn_gelu_kernel(const float* __restrict__ dww, const float* __restrict__ dwb,
                                  const float* __restrict__ gamma, const float* __restrict__ beta,
                                  const float* __restrict__ mean, const float* __restrict__ var) {
    int p = blockIdx.x, b = blockIdx.y, c = threadIdx.x;
    int py = p / PP, px = p % PP;
    float acc = dwb[c];
#pragma unroll
    for (int dy = 0; dy < 3; dy++) {
        int iy = py - 1 + dy;
        if ((unsigned)iy >= PP) continue;
#pragma unroll
        for (int dx = 0; dx < 3; dx++) {
            int ix = px - 1 + dx;
            if ((unsigned)ix >= PP) continue;
            acc += dww[c * 9 + dy * 3 + dx] *
                   g_xpool[((size_t)b * NPOS + iy * PP + ix) * DIM + c];
        }
    }
    acc = (acc - mean[c]) * (gamma[c] * rsqrtf(var[c] + 1e-5f)) + beta[c];
    acc = 0.5f * acc * (1.f + erff(acc * 0.70710678118654752f));
    g_vmid[((size_t)b * NPOS + p) * DIM + c] = acc;
}

// ---------------- generic tiled GEMM: C[M,N] = A[M,K] * B[N,K]^T + bias ----
// M % 64 == 0, N % 64 == 0, K % 16 == 0 (true for both uses)
__global__ void gemm64_kernel(const float* __restrict__ A, const float* __restrict__ B,
                              const float* __restrict__ bias, float* __restrict__ C,
                              int M, int N, int K) {
    __shared__ float As[16][64];
    __shared__ float Bs[16][64];
    int tid = threadIdx.x;
    int tx = tid & 15, ty = tid >> 4;
    int m0 = blockIdx.y * 64, n0 = blockIdx.x * 64;
    int lr = tid >> 2;           // 0..63 row within tile
    int lk = (tid & 3) << 2;     // 0,4,8,12
    float acc[4][4] = {};
    for (int k0 = 0; k0 < K; k0 += 16) {
        float4 a4 = *(const float4*)&A[(size_t)(m0 + lr) * K + k0 + lk];
        float4 b4 = *(const float4*)&B[(size_t)(n0 + lr) * K + k0 + lk];
        As[lk + 0][lr] = a4.x; As[lk + 1][lr] = a4.y; As[lk + 2][lr] = a4.z; As[lk + 3][lr] = a4.w;
        Bs[lk + 0][lr] = b4.x; Bs[lk + 1][lr] = b4.y; Bs[lk + 2][lr] = b4.z; Bs[lk + 3][lr] = b4.w;
        __syncthreads();
#pragma unroll
        for (int k = 0; k < 16; k++) {
            float4 av = *(const float4*)&As[k][ty * 4];
            float4 bv = *(const float4*)&Bs[k][tx * 4];
            float a[4] = {av.x, av.y, av.z, av.w};
            float bb[4] = {bv.x, bv.y, bv.z, bv.w};
#pragma unroll
            for (int i = 0; i < 4; i++)
#pragma unroll
                for (int j = 0; j < 4; j++)
                    acc[i][j] = fmaf(a[i], bb[j], acc[i][j]);
        }
        __syncthreads();
    }
    float4 bias4 = *(const float4*)&bias[n0 + tx * 4];
#pragma unroll
    for (int i = 0; i < 4; i++) {
        float4 o;
        o.x = acc[i][0] + bias4.x;
        o.y = acc[i][1] + bias4.y;
        o.z = acc[i][2] + bias4.z;
        o.w = acc[i][3] + bias4.w;
        *(float4*)&C[(size_t)(m0 + ty * 4 + i) * N + n0 + tx * 4] = o;
    }
}

// ---------------- 5) attention per (b,h): K,V resident in smem -------------
// scores s_ij = (qx_i*kx_j + qy_i*ky_j) * 0.125 ; softmax over j ; O = P @ V
__global__ void attn_kernel() {
    extern __shared__ float smem[];
    float* v_s = smem;                    // [784][64]
    float* kx_s = smem + NPOS * DH;       // [784]
    float* ky_s = kx_s + NPOS;            // [784]
    int h = blockIdx.x, b = blockIdx.y;
    int tid = threadIdx.x, lane = tid & 31, w = tid >> 5;
    int nthreads = blockDim.x, nwarps = nthreads >> 5;

    const float* vsrc = g_v + (size_t)b * NPOS * INNER + h * DH;
    for (int i = tid; i < NPOS * (DH / 4); i += nthreads) {
        int n = i >> 4, d4 = (i & 15) << 2;
        *(float4*)&v_s[n * DH + d4] = *(const float4*)&vsrc[(size_t)n * INNER + d4];
    }
    const float* ksrc = g_k + ((size_t)b * HEADS + h) * NPOS * 2;
    for (int i = tid; i < NPOS; i += nthreads) {
        float2 kv = *(const float2*)&ksrc[i * 2];
        kx_s[i] = kv.x; ky_s[i] = kv.y;
    }
    __syncthreads();

    const float* qsrc = g_q + ((size_t)b * HEADS + h) * NPOS * 2;
    float* odst = g_ao + (size_t)b * NPOS * INNER + h * DH;
    const float scale = 0.125f;
    const int NTILES = (NPOS + 31) / 32;  // 25

    for (int t = w; t < NTILES; t += nwarps) {
        int qi = t * 32 + lane;
        bool active = qi < NPOS;
        float qx = 0.f, qy = 0.f;
        if (active) {
            float2 qv = *(const float2*)&qsrc[qi * 2];
            qx = qv.x * scale; qy = qv.y * scale;
        }
        // pass 1: max
        float m = -1e30f;
#pragma unroll 4
        for (int j = 0; j < NPOS; j++) {
            float s = fmaf(qx, kx_s[j], qy * ky_s[j]);
            m = fmaxf(m, s);
        }
        // pass 2: exp-sum + P@V accumulation (lane owns dim pair 2*lane)
        float l = 0.f;
        float2 acc[32];
#pragma unroll
        for (int qq = 0; qq < 32; qq++) { acc[qq].x = 0.f; acc[qq].y = 0.f; }
        for (int j = 0; j < NPOS; j++) {
            float s = fmaf(qx, kx_s[j], qy * ky_s[j]);
            float p = __expf(s - m);
            p = active ? p : 0.f;
            l += p;
            float2 vv = *(const float2*)&v_s[j * DH + 2 * lane];
#pragma unroll
            for (int qq = 0; qq < 32; qq++) {
                float pq = __shfl_sync(0xffffffffu, p, qq);
                acc[qq].x = fmaf(pq, vv.x, acc[qq].x);
                acc[qq].y = fmaf(pq, vv.y, acc[qq].y);
            }
        }
#pragma unroll
        for (int qq = 0; qq < 32; qq++) {
            float lq = __shfl_sync(0xffffffffu, l, qq);
            int q = t * 32 + qq;
            if (q < NPOS) {
                float inv = 1.f / lq;
                float2 o;
                o.x = acc[qq].x * inv;
                o.y = acc[qq].y * inv;
                *(float2*)&odst[(size_t)q * INNER + 2 * lane] = o;
            }
        }
    }
}

// ---------------- 7) bicubic x2 upsample (align_corners=False, a=-0.75) ----
__global__ void upsample_kernel(float* __restrict__ out) {
    extern __shared__ float rows[];   // [4][28][256]
    int oy = blockIdx.x, b = blockIdx.y, c = threadIdx.x;
    int iy0; const float* wy;
    if (oy & 1) { iy0 = (oy - 1) >> 1; wy = c_W25; }
    else        { iy0 = (oy >> 1) - 1; wy = c_W75; }
#pragma unroll
    for (int r = 0; r < 4; r++) {
        int sy = min(max(iy0 - 1 + r, 0), PP - 1);
        const float* src = &g_y28[((size_t)b * NPOS + sy * PP) * DIM];
        for (int i = c; i < PP * DIM; i += 256) rows[r * PP * DIM + i] = src[i];
    }
    __syncthreads();
    for (int ox = 0; ox < IMG; ox++) {
        int ix0; const float* wx;
        if (ox & 1) { ix0 = (ox - 1) >> 1; wx = c_W25; }
        else        { ix0 = (ox >> 1) - 1; wx = c_W75; }
        int sx0 = min(max(ix0 - 1, 0), PP - 1);
        int sx1 = min(max(ix0 + 0, 0), PP - 1);
        int sx2 = min(max(ix0 + 1, 0), PP - 1);
        int sx3 = min(max(ix0 + 2, 0), PP - 1);
        float acc = 0.f;
#pragma unroll
        for (int r = 0; r < 4; r++) {
            const float* rp = &rows[r * PP * DIM];
            float hsum = wx[0] * rp[sx0 * DIM + c]
                       + wx[1] * rp[sx1 * DIM + c]
                       + wx[2] * rp[sx2 * DIM + c]
                       + wx[3] * rp[sx3 * DIM + c];
            acc = fmaf(wy[r], hsum, acc);
        }
        out[((size_t)b * IMG * IMG + oy * IMG + ox) * DIM + c] = acc;
    }
}

// ---------------- launch ---------------------------------------------------
extern "C" void kernel_launch(void* const* d_in, const int* in_sizes, int n_in,
                              void* d_out, int out_size) {
    const float* x     = (const float*)d_in[0];
    const float* q_w   = (const float*)d_in[1];
    const float* q_b   = (const float*)d_in[2];
    const float* k_w   = (const float*)d_in[3];
    const float* k_b   = (const float*)d_in[4];
    const float* dw_w  = (const float*)d_in[5];
    const float* dw_b  = (const float*)d_in[6];
    const float* bn_g  = (const float*)d_in[7];
    const float* bn_b  = (const float*)d_in[8];
    const float* bn_m  = (const float*)d_in[9];
    const float* bn_v  = (const float*)d_in[10];
    const float* pw_w  = (const float*)d_in[11];
    const float* pw_b  = (const float*)d_in[12];
    const float* out_w = (const float*)d_in[13];
    const float* out_b = (const float*)d_in[14];
    float* out = (float*)d_out;

    const int ATTN_SMEM = (NPOS * DH + 2 * NPOS) * (int)sizeof(float);  // 206976
    const int UPS_SMEM  = 4 * PP * DIM * (int)sizeof(float);            // 114688
    cudaFuncSetAttribute(attn_kernel, cudaFuncAttributeMaxDynamicSharedMemorySize, ATTN_SMEM);
    cudaFuncSetAttribute(upsample_kernel, cudaFuncAttributeMaxDynamicSharedMemorySize, UPS_SMEM);

    void *p_vmid, *p_v, *p_ao, *p_y28;
    cudaGetSymbolAddress(&p_vmid, g_vmid);
    cudaGetSymbolAddress(&p_v, g_v);
    cudaGetSymbolAddress(&p_ao, g_ao);
    cudaGetSymbolAddress(&p_y28, g_y28);

    pool_stats_kernel<<<dim3(NPOS, BATCH), 256>>>(x);
    qk_conv_kernel<<<dim3(NPOS, BATCH), 32>>>(q_w, q_b, k_w, k_b);
    dw_bn_gelu_kernel<<<dim3(NPOS, BATCH), 256>>>(dw_w, dw_b, bn_g, bn_b, bn_m, bn_v);
    // pointwise conv: [12544,256] x [512,256]^T -> [12544,512]
    gemm64_kernel<<<dim3(INNER / 64, (BATCH * NPOS) / 64), 256>>>(
        (const float*)p_vmid, pw_w, pw_b, (float*)p_v, BATCH * NPOS, INNER, DIM);
    attn_kernel<<<dim3(HEADS, BATCH), 512, ATTN_SMEM>>>();
    // output projection: [12544,512] x [256,512]^T -> [12544,256]
    gemm64_kernel<<<dim3(DIM / 64, (BATCH * NPOS) / 64), 256>>>(
        (const float*)p_ao, out_w, out_b, (float*)p_y28, BATCH * NPOS, DIM, INNER);
    upsample_kernel<<<dim3(IMG, BATCH), 256, UPS_SMEM>>>(out);
}

// round 2
// speedup vs baseline: 2.3338x; 2.3338x over previous
#include <cuda_runtime.h>
#include <math.h>
#include <stdint.h>

#define BATCH 16
#define IMG 56
#define PP 28
#define NPOS 784
#define DIM 256
#define HEADS 8
#define DH 64
#define INNER 512

// ---------------- scratch (static device allocations; no cudaMalloc) -------
__device__ float g_xpool[BATCH * NPOS * DIM];   // pooled, channel-last [b, p, c]
__device__ float g_attn2[BATCH * NPOS * 2];     // mean/max over channels
__device__ float g_q[BATCH * HEADS * NPOS * 2];
__device__ float g_k[BATCH * HEADS * NPOS * 2];
__device__ float g_vmid[BATCH * NPOS * DIM];    // after dw+BN+GELU
__device__ float g_v[BATCH * NPOS * INNER];     // after pointwise conv [b,p,ch]
__device__ float g_ao[BATCH * NPOS * INNER];    // attention out [b,p,h*64+d]
__device__ float g_y28[BATCH * NPOS * DIM];     // after out-proj [b,p,c]

// bicubic (a=-0.75) weights for t=0.25 and t=0.75 (half-pixel, x2)
__constant__ float c_W25[4] = {-0.10546875f, 0.87890625f, 0.26171875f, -0.03515625f};
__constant__ float c_W75[4] = {-0.03515625f, 0.26171875f, 0.87890625f, -0.10546875f};

// ---------------- tf32 helpers ---------------------------------------------
__device__ __forceinline__ uint32_t f2tf(float f) {
    uint32_t u;
    asm("cvt.rna.tf32.f32 %0, %1;" : "=r"(u) : "f"(f));
    return u;
}

__device__ __forceinline__ void mma4(float c[4], uint32_t a0, uint32_t a1,
                                     uint32_t a2, uint32_t a3,
                                     uint32_t b0, uint32_t b1) {
    asm volatile(
        "mma.sync.aligned.m16n8k8.row.col.f32.tf32.tf32.f32 "
        "{%0,%1,%2,%3},{%4,%5,%6,%7},{%8,%9},{%0,%1,%2,%3};"
        : "+f"(c[0]), "+f"(c[1]), "+f"(c[2]), "+f"(c[3])
        : "r"(a0), "r"(a1), "r"(a2), "r"(a3), "r"(b0), "r"(b1));
}

// ---------------- 1) avgpool(3,2,1) + channel mean/max ---------------------
__global__ void pool_stats_kernel(const float* __restrict__ x) {
    int p = blockIdx.x, b = blockIdx.y, c = threadIdx.x;
    int py = p / PP, px = p % PP;
    float acc = 0.f;
#pragma unroll
    for (int wy = 0; wy < 3; wy++) {
        int iy = 2 * py - 1 + wy;
        if ((unsigned)iy >= IMG) continue;
#pragma unroll
        for (int wx = 0; wx < 3; wx++) {
            int ix = 2 * px - 1 + wx;
            if ((unsigned)ix >= IMG) continue;
            acc += x[((size_t)b * IMG * IMG + iy * IMG + ix) * DIM + c];
        }
    }
    float pool = acc * (1.f / 9.f);
    g_xpool[((size_t)b * NPOS + p) * DIM + c] = pool;

    float vs = pool, vm = pool;
#pragma unroll
    for (int o = 16; o > 0; o >>= 1) {
        vs += __shfl_down_sync(0xffffffffu, vs, o);
        vm = fmaxf(vm, __shfl_down_sync(0xffffffffu, vm, o));
    }
    __shared__ float ss[8], sm[8];
    int lane = c & 31, w = c >> 5;
    if (lane == 0) { ss[w] = vs; sm[w] = vm; }
    __syncthreads();
    if (c == 0) {
        float S = ss[0], M = sm[0];
#pragma unroll
        for (int i = 1; i < 8; i++) { S += ss[i]; M = fmaxf(M, sm[i]); }
        g_attn2[((size_t)b * NPOS + p) * 2 + 0] = S * (1.f / DIM);
        g_attn2[((size_t)b * NPOS + p) * 2 + 1] = M;
    }
}

// ---------------- 2) q/k 3x3 convs on the 2-channel attention map ----------
__global__ void qk_conv_kernel(const float* __restrict__ qw, const float* __restrict__ qb,
                               const float* __restrict__ kw, const float* __restrict__ kb) {
    int p = blockIdx.x, b = blockIdx.y, t = threadIdx.x;
    int sel = t >> 4, och = t & 15;
    const float* w = sel ? kw : qw;
    const float* bi = sel ? kb : qb;
    float* outp = sel ? g_k : g_q;
    int py = p / PP, px = p % PP;
    float acc = bi[och];
#pragma unroll
    for (int dy = 0; dy < 3; dy++) {
        int iy = py - 1 + dy;
        if ((unsigned)iy >= PP) continue;
#pragma unroll
        for (int dx = 0; dx < 3; dx++) {
            int ix = px - 1 + dx;
            if ((unsigned)ix >= PP) continue;
            const float* a2 = &g_attn2[((size_t)b * NPOS + iy * PP + ix) * 2];
            acc += w[((och * 2 + 0) * 3 + dy) * 3 + dx] * a2[0]
                 + w[((och * 2 + 1) * 3 + dy) * 3 + dx] * a2[1];
        }
    }
    int h = och >> 1, comp = och & 1;
    outp[(((size_t)b * HEADS + h) * NPOS + p) * 2 + comp] = acc;
}

// ---------------- 3) depthwise 3x3 + BN(eval) + exact GELU -----------------
__global__ void dw_bn_gelu_kernel(const float* __restrict__ dww, const float* __restrict__ dwb,
                                  const float* __restrict__ gamma, const float* __restrict__ beta,
                                  const float* __restrict__ mean, const float* __restrict__ var) {
    int p = blockIdx.x, b = blockIdx.y, c = threadIdx.x;
    int py = p / PP, px = p % PP;
    float acc = dwb[c];
#pragma unroll
    for (int dy = 0; dy < 3; dy++) {
        int iy = py - 1 + dy;
        if ((unsigned)iy >= PP) continue;
#pragma unroll
        for (int dx = 0; dx < 3; dx++) {
            int ix = px - 1 + dx;
            if ((unsigned)ix >= PP) continue;
            acc += dww[c * 9 + dy * 3 + dx] *
                   g_xpool[((size_t)b * NPOS + iy * PP + ix) * DIM + c];
        }
    }
    acc = (acc - mean[c]) * (gamma[c] * rsqrtf(var[c] + 1e-5f)) + beta[c];
    acc = 0.5f * acc * (1.f + erff(acc * 0.70710678118654752f));
    g_vmid[((size_t)b * NPOS + p) * DIM + c] = acc;
}

// ---------------- mma tf32 GEMM: C[M,N] = A[M,K] * B[N,K]^T + bias ---------
// block tile 128x64, 256 threads (8 warps, 4x2), K-chunk 32. M%128==0, N%64==0, K%32==0.
__global__ void gemm_mma_kernel(const float* __restrict__ A, const float* __restrict__ B,
                                const float* __restrict__ bias, float* __restrict__ C,
                                int M, int N, int K) {
    __shared__ uint2 Ap[4][128][4];   // [kgroup][row][tig] = (A[r][k], A[r][k+4]) tf32
    __shared__ uint2 Bp[4][64][4];
    int tid = threadIdx.x;
    int lane = tid & 31, w = tid >> 5, g = lane >> 2, tig = lane & 3;
    int wm = w >> 1, wn = w & 1;
    int m0 = blockIdx.y * 128, n0 = blockIdx.x * 64;
    float c[2][4][4] = {};

    int nchunks = K >> 5;
    int ar[4], ac4[4], br[2], bc4[2];
    float4 ra[4], rb[2];
#pragma unroll
    for (int i = 0; i < 4; i++) { int id = tid + i * 256; ar[i] = id >> 3; ac4[i] = id & 7; }
#pragma unroll
    for (int i = 0; i < 2; i++) { int id = tid + i * 256; br[i] = id >> 3; bc4[i] = id & 7; }

#pragma unroll
    for (int i = 0; i < 4; i++)
        ra[i] = *(const float4*)&A[(size_t)(m0 + ar[i]) * K + ac4[i] * 4];
#pragma unroll
    for (int i = 0; i < 2; i++)
        rb[i] = *(const float4*)&B[(size_t)(n0 + br[i]) * K + bc4[i] * 4];

    for (int kc = 0; kc < nchunks; kc++) {
#pragma unroll
        for (int i = 0; i < 4; i++) {
            int kg = ac4[i] >> 1, half = ac4[i] & 1;
            uint32_t* dst = (uint32_t*)&Ap[kg][ar[i]][0];
            dst[0 + half] = f2tf(ra[i].x); dst[2 + half] = f2tf(ra[i].y);
            dst[4 + half] = f2tf(ra[i].z); dst[6 + half] = f2tf(ra[i].w);
        }
#pragma unroll
        for (int i = 0; i < 2; i++) {
            int kg = bc4[i] >> 1, half = bc4[i] & 1;
            uint32_t* dst = (uint32_t*)&Bp[kg][br[i]][0];
            dst[0 + half] = f2tf(rb[i].x); dst[2 + half] = f2tf(rb[i].y);
            dst[4 + half] = f2tf(rb[i].z); dst[6 + half] = f2tf(rb[i].w);
        }
        __syncthreads();
        if (kc + 1 < nchunks) {
            int ko = (kc + 1) * 32;
#pragma unroll
            for (int i = 0; i < 4; i++)
                ra[i] = *(const float4*)&A[(size_t)(m0 + ar[i]) * K + ko + ac4[i] * 4];
#pragma unroll
            for (int i = 0; i < 2; i++)
                rb[i] = *(const float4*)&B[(size_t)(n0 + br[i]) * K + ko + bc4[i] * 4];
        }
#pragma unroll
        for (int ks = 0; ks < 4; ks++) {
            uint2 aL0 = Ap[ks][wm * 32 + g][tig];
            uint2 aH0 = Ap[ks][wm * 32 + 8 + g][tig];
            uint2 aL1 = Ap[ks][wm * 32 + 16 + g][tig];
            uint2 aH1 = Ap[ks][wm * 32 + 24 + g][tig];
#pragma unroll
            for (int nt = 0; nt < 4; nt++) {
                uint2 bb = Bp[ks][wn * 32 + nt * 8 + g][tig];
                mma4(c[0][nt], aL0.x, aH0.x, aL0.y, aH0.y, bb.x, bb.y);
                mma4(c[1][nt], aL1.x, aH1.x, aL1.y, aH1.y, bb.x, bb.y);
            }
        }
        __syncthreads();
    }
#pragma unroll
    for (int mt = 0; mt < 2; mt++) {
        int r = m0 + wm * 32 + mt * 16 + g;
#pragma unroll
        for (int nt = 0; nt < 4; nt++) {
            int n = n0 + wn * 32 + nt * 8 + 2 * tig;
            float bx = bias[n], by = bias[n + 1];
            *(float2*)&C[(size_t)r * N + n] = make_float2(c[mt][nt][0] + bx, c[mt][nt][1] + by);
            *(float2*)&C[(size_t)(r + 8) * N + n] = make_float2(c[mt][nt][2] + bx, c[mt][nt][3] + by);
        }
    }
}

// ---------------- 5) attention per (b,h) via tf32 mma ----------------------
// scores computed analytically into A fragments; V tf32-packed in smem;
// softmax shift m_i = |qx|max|kx| + |qy|max|ky| (exact-safe, no max pass).
__global__ void attn_mma_kernel() {
    extern __shared__ float smem[];
    uint2* Vp = (uint2*)smem;                      // [98][64][4] pairs (k, k+4): 200704 B
    float* kx_s = smem + (98 * 64 * 4 * 2);        // 784 floats
    float* ky_s = kx_s + NPOS;
    __shared__ float red[16];
    int h = blockIdx.x, b = blockIdx.y;
    int tid = threadIdx.x, lane = tid & 31, w = tid >> 5;
    int g = lane >> 2, tig = lane & 3;

    const float* vsrc = g_v + (size_t)b * NPOS * INNER + h * DH;
    for (int i = tid; i < NPOS * DH; i += 256) {
        int j = i >> 6, n = i & 63;
        uint32_t tv = f2tf(vsrc[(size_t)j * INNER + n]);
        int jg = j >> 3, kk = j & 7;
        uint32_t* cell = (uint32_t*)&Vp[(jg * 64 + n) * 4 + (kk & 3)];
        cell[kk >> 2] = tv;
    }
    const float* ksrc = g_k + ((size_t)b * HEADS + h) * NPOS * 2;
    float axm = 0.f, aym = 0.f;
    for (int i = tid; i < NPOS; i += 256) {
        float2 kv = ((const float2*)ksrc)[i];
        float kx = kv.x * 0.125f, ky = kv.y * 0.125f;
        kx_s[i] = kx; ky_s[i] = ky;
        axm = fmaxf(axm, fabsf(kx)); aym = fmaxf(aym, fabsf(ky));
    }
#pragma unroll
    for (int o = 16; o > 0; o >>= 1) {
        axm = fmaxf(axm, __shfl_xor_sync(0xffffffffu, axm, o));
        aym = fmaxf(aym, __shfl_xor_sync(0xffffffffu, aym, o));
    }
    if (lane == 0) { red[w] = axm; red[8 + w] = aym; }
    __syncthreads();
    float Mx = red[0], My = red[8];
#pragma unroll
    for (int i = 1; i < 8; i++) { Mx = fmaxf(Mx, red[i]); My = fmaxf(My, red[8 + i]); }

    const float2* qsrc = (const float2*)(g_q + ((size_t)b * HEADS + h) * NPOS * 2);
    float* odst = g_ao + (size_t)b * NPOS * INNER + h * DH;

    for (int t = w; t < 49; t += 8) {
        int r0 = t * 16 + g, r1 = r0 + 8;
        float2 q0 = qsrc[r0], q1 = qsrc[r1];
        float m0v = fabsf(q0.x) * Mx + fabsf(q0.y) * My;
        float m1v = fabsf(q1.x) * Mx + fabsf(q1.y) * My;
        float c[8][4];
#pragma unroll
        for (int nt = 0; nt < 8; nt++)
#pragma unroll
            for (int e = 0; e < 4; e++) c[nt][e] = 0.f;
        float la = 0.f, lb = 0.f;
        for (int jg = 0; jg < 98; jg++) {
            int ja = jg * 8 + tig, jb2 = ja + 4;
            float kxa = kx_s[ja], kya = ky_s[ja];
            float kxb = kx_s[jb2], kyb = ky_s[jb2];
            float p0 = __expf(fmaf(q0.x, kxa, q0.y * kya) - m0v);
            float p1 = __expf(fmaf(q1.x, kxa, q1.y * kya) - m1v);
            float p2 = __expf(fmaf(q0.x, kxb, q0.y * kyb) - m0v);
            float p3 = __expf(fmaf(q1.x, kxb, q1.y * kyb) - m1v);
            la += p0 + p2; lb += p1 + p3;
            uint32_t a0 = f2tf(p0), a1 = f2tf(p1), a2 = f2tf(p2), a3 = f2tf(p3);
            const uint2* vrow = &Vp[(size_t)jg * 256 + tig];
#pragma unroll
            for (int nt = 0; nt < 8; nt++) {
                uint2 bb = vrow[(nt * 8 + g) * 4];
                mma4(c[nt], a0, a1, a2, a3, bb.x, bb.y);
            }
        }
        la += __shfl_xor_sync(0xffffffffu, la, 1);
        la += __shfl_xor_sync(0xffffffffu, la, 2);
        lb += __shfl_xor_sync(0xffffffffu, lb, 1);
        lb += __shfl_xor_sync(0xffffffffu, lb, 2);
        float i0 = 1.f / la, i1 = 1.f / lb;
#pragma unroll
        for (int nt = 0; nt < 8; nt++) {
            *(float2*)&odst[(size_t)r0 * INNER + nt * 8 + 2 * tig] =
                make_float2(c[nt][0] * i0, c[nt][1] * i0);
            *(float2*)&odst[(size_t)r1 * INNER + nt * 8 + 2 * tig] =
                make_float2(c[nt][2] * i1, c[nt][3] * i1);
        }
    }
}

// ---------------- 7) bicubic x2 upsample (align_corners=False, a=-0.75) ----
__global__ void upsample_kernel(float* __restrict__ out) {
    extern __shared__ float rows[];   // [4][28][256]
    int oy = blockIdx.x, b = blockIdx.y, c = threadIdx.x;
    int iy0; const float* wy;
    if (oy & 1) { iy0 = (oy - 1) >> 1; wy = c_W25; }
    else        { iy0 = (oy >> 1) - 1; wy = c_W75; }
#pragma unroll
    for (int r = 0; r < 4; r++) {
        int sy = min(max(iy0 - 1 + r, 0), PP - 1);
        const float* src = &g_y28[((size_t)b * NPOS + sy * PP) * DIM];
        for (int i = c; i < PP * DIM; i += 256) rows[r * PP * DIM + i] = src[i];
    }
    __syncthreads();
    for (int ox = 0; ox < IMG; ox++) {
        int ix0; const float* wx;
        if (ox & 1) { ix0 = (ox - 1) >> 1; wx = c_W25; }
        else        { ix0 = (ox >> 1) - 1; wx = c_W75; }
        int sx0 = min(max(ix0 - 1, 0), PP - 1);
        int sx1 = min(max(ix0 + 0, 0), PP - 1);
        int sx2 = min(max(ix0 + 1, 0), PP - 1);
        int sx3 = min(max(ix0 + 2, 0), PP - 1);
        float acc = 0.f;
#pragma unroll
        for (int r = 0; r < 4; r++) {
            const float* rp = &rows[r * PP * DIM];
            float hsum = wx[0] * rp[sx0 * DIM + c]
                       + wx[1] * rp[sx1 * DIM + c]
                       + wx[2] * rp[sx2 * DIM + c]
                       + wx[3] * rp[sx3 * DIM + c];
            acc = fmaf(wy[r], hsum, acc);
        }
        out[((size_t)b * IMG * IMG + oy * IMG + ox) * DIM + c] = acc;
    }
}

// ---------------- launch ---------------------------------------------------
extern "C" void kernel_launch(void* const* d_in, const int* in_sizes, int n_in,
                              void* d_out, int out_size) {
    const float* x     = (const float*)d_in[0];
    const float* q_w   = (const float*)d_in[1];
    const float* q_b   = (const float*)d_in[2];
    const float* k_w   = (const float*)d_in[3];
    const float* k_b   = (const float*)d_in[4];
    const float* dw_w  = (const float*)d_in[5];
    const float* dw_b  = (const float*)d_in[6];
    const float* bn_g  = (const float*)d_in[7];
    const float* bn_b  = (const float*)d_in[8];
    const float* bn_m  = (const float*)d_in[9];
    const float* bn_v  = (const float*)d_in[10];
    const float* pw_w  = (const float*)d_in[11];
    const float* pw_b  = (const float*)d_in[12];
    const float* out_w = (const float*)d_in[13];
    const float* out_b = (const float*)d_in[14];
    float* out = (float*)d_out;

    const int ATTN_SMEM = 98 * 64 * 4 * 8 + 2 * NPOS * 4;            // 206976
    const int UPS_SMEM  = 4 * PP * DIM * (int)sizeof(float);         // 114688
    cudaFuncSetAttribute(attn_mma_kernel, cudaFuncAttributeMaxDynamicSharedMemorySize, ATTN_SMEM);
    cudaFuncSetAttribute(upsample_kernel, cudaFuncAttributeMaxDynamicSharedMemorySize, UPS_SMEM);

    void *p_vmid, *p_v, *p_ao, *p_y28;
    cudaGetSymbolAddress(&p_vmid, g_vmid);
    cudaGetSymbolAddress(&p_v, g_v);
    cudaGetSymbolAddress(&p_ao, g_ao);
    cudaGetSymbolAddress(&p_y28, g_y28);

    pool_stats_kernel<<<dim3(NPOS, BATCH), 256>>>(x);
    qk_conv_kernel<<<dim3(NPOS, BATCH), 32>>>(q_w, q_b, k_w, k_b);
    dw_bn_gelu_kernel<<<dim3(NPOS, BATCH), 256>>>(dw_w, dw_b, bn_g, bn_b, bn_m, bn_v);
    // pointwise conv: [12544,256] x [512,256]^T -> [12544,512]
    gemm_mma_kernel<<<dim3(INNER / 64, (BATCH * NPOS) / 128), 256>>>(
        (const float*)p_vmid, pw_w, pw_b, (float*)p_v, BATCH * NPOS, INNER, DIM);
    attn_mma_kernel<<<dim3(HEADS, BATCH), 256, ATTN_SMEM>>>();
    // output projection: [12544,512] x [256,512]^T -> [12544,256]
    gemm_mma_kernel<<<dim3(DIM / 64, (BATCH * NPOS) / 128), 256>>>(
        (const float*)p_ao, out_w, out_b, (float*)p_y28, BATCH * NPOS, DIM, INNER);
    upsample_kernel<<<dim3(IMG, BATCH), 256, UPS_SMEM>>>(out);
}

// round 3
// speedup vs baseline: 2.5655x; 1.0993x over previous
#include <cuda_runtime.h>
#include <math.h>
#include <stdint.h>

#define BATCH 16
#define IMG 56
#define PP 28
#define NPOS 784
#define DIM 256
#define HEADS 8
#define DH 64
#define INNER 512

// ---------------- scratch (static device allocations; no cudaMalloc) -------
__device__ float g_xpool[BATCH * NPOS * DIM];   // pooled, channel-last [b, p, c]
__device__ float g_attn2[BATCH * NPOS * 2];     // mean/max over channels
__device__ float g_q[BATCH * HEADS * NPOS * 2];
__device__ float g_k[BATCH * HEADS * NPOS * 2];
__device__ float g_vmid[BATCH * NPOS * DIM];    // after dw+BN+GELU (tf32-rounded)
__device__ float g_v[BATCH * NPOS * INNER];     // after pointwise conv (tf32-rounded)
__device__ float g_ao[BATCH * NPOS * INNER];    // attention out (tf32-rounded)
__device__ float g_y28[BATCH * NPOS * DIM];     // after out-proj [b,p,c]
__device__ float g_pww[INNER * DIM];            // tf32-rounded pw_w
__device__ float g_oww[DIM * INNER];            // tf32-rounded out_w

// bicubic (a=-0.75) weights for t=0.25 and t=0.75 (half-pixel, x2)
__constant__ float c_W25[4] = {-0.10546875f, 0.87890625f, 0.26171875f, -0.03515625f};
__constant__ float c_W75[4] = {-0.03515625f, 0.26171875f, 0.87890625f, -0.10546875f};

// ---------------- tf32 helpers ---------------------------------------------
__device__ __forceinline__ uint32_t f2tf(float f) {
    uint32_t u;
    asm("cvt.rna.tf32.f32 %0, %1;" : "=r"(u) : "f"(f));
    return u;
}
__device__ __forceinline__ float roundtf(float f) {
    return __uint_as_float(f2tf(f));
}

__device__ __forceinline__ void mma4(float c[4], uint32_t a0, uint32_t a1,
                                     uint32_t a2, uint32_t a3,
                                     uint32_t b0, uint32_t b1) {
    asm volatile(
        "mma.sync.aligned.m16n8k8.row.col.f32.tf32.tf32.f32 "
        "{%0,%1,%2,%3},{%4,%5,%6,%7},{%8,%9},{%0,%1,%2,%3};"
        : "+f"(c[0]), "+f"(c[1]), "+f"(c[2]), "+f"(c[3])
        : "r"(a0), "r"(a1), "r"(a2), "r"(a3), "r"(b0), "r"(b1));
}

// ---------------- 0) round weights to tf32 once ----------------------------
__global__ void round_weights_kernel(const float* __restrict__ pw,
                                     const float* __restrict__ ow) {
    int i = blockIdx.x * 256 + threadIdx.x;
    if (i < INNER * DIM) {
        g_pww[i] = roundtf(pw[i]);
        g_oww[i] = roundtf(ow[i]);
    }
}

// ---------------- 1) avgpool(3,2,1) + channel mean/max ---------------------
__global__ void pool_stats_kernel(const float* __restrict__ x) {
    int p = blockIdx.x, b = blockIdx.y, c = threadIdx.x;
    int py = p / PP, px = p % PP;
    float acc = 0.f;
#pragma unroll
    for (int wy = 0; wy < 3; wy++) {
        int iy = 2 * py - 1 + wy;
        if ((unsigned)iy >= IMG) continue;
#pragma unroll
        for (int wx = 0; wx < 3; wx++) {
            int ix = 2 * px - 1 + wx;
            if ((unsigned)ix >= IMG) continue;
            acc += x[((size_t)b * IMG * IMG + iy * IMG + ix) * DIM + c];
        }
    }
    float pool = acc * (1.f / 9.f);
    g_xpool[((size_t)b * NPOS + p) * DIM + c] = pool;

    float vs = pool, vm = pool;
#pragma unroll
    for (int o = 16; o > 0; o >>= 1) {
        vs += __shfl_down_sync(0xffffffffu, vs, o);
        vm = fmaxf(vm, __shfl_down_sync(0xffffffffu, vm, o));
    }
    __shared__ float ss[8], sm[8];
    int lane = c & 31, w = c >> 5;
    if (lane == 0) { ss[w] = vs; sm[w] = vm; }
    __syncthreads();
    if (c == 0) {
        float S = ss[0], M = sm[0];
#pragma unroll
        for (int i = 1; i < 8; i++) { S += ss[i]; M = fmaxf(M, sm[i]); }
        g_attn2[((size_t)b * NPOS + p) * 2 + 0] = S * (1.f / DIM);
        g_attn2[((size_t)b * NPOS + p) * 2 + 1] = M;
    }
}

// ---------------- 2) q/k 3x3 convs on the 2-channel attention map ----------
__global__ void qk_conv_kernel(const float* __restrict__ qw, const float* __restrict__ qb,
                               const float* __restrict__ kw, const float* __restrict__ kb) {
    int p = blockIdx.x, b = blockIdx.y, t = threadIdx.x;
    int sel = t >> 4, och = t & 15;
    const float* w = sel ? kw : qw;
    const float* bi = sel ? kb : qb;
    float* outp = sel ? g_k : g_q;
    int py = p / PP, px = p % PP;
    float acc = bi[och];
#pragma unroll
    for (int dy = 0; dy < 3; dy++) {
        int iy = py - 1 + dy;
        if ((unsigned)iy >= PP) continue;
#pragma unroll
        for (int dx = 0; dx < 3; dx++) {
            int ix = px - 1 + dx;
            if ((unsigned)ix >= PP) continue;
            const float* a2 = &g_attn2[((size_t)b * NPOS + iy * PP + ix) * 2];
            acc += w[((och * 2 + 0) * 3 + dy) * 3 + dx] * a2[0]
                 + w[((och * 2 + 1) * 3 + dy) * 3 + dx] * a2[1];
        }
    }
    int h = och >> 1, comp = och & 1;
    outp[(((size_t)b * HEADS + h) * NPOS + p) * 2 + comp] = acc;
}

// ---------------- 3) depthwise 3x3 + BN(eval) + exact GELU (tf32 out) ------
__global__ void dw_bn_gelu_kernel(const float* __restrict__ dww, const float* __restrict__ dwb,
                                  const float* __restrict__ gamma, const float* __restrict__ beta,
                                  const float* __restrict__ mean, const float* __restrict__ var) {
    int p = blockIdx.x, b = blockIdx.y, c = threadIdx.x;
    int py = p / PP, px = p % PP;
    float acc = dwb[c];
#pragma unroll
    for (int dy = 0; dy < 3; dy++) {
        int iy = py - 1 + dy;
        if ((unsigned)iy >= PP) continue;
#pragma unroll
        for (int dx = 0; dx < 3; dx++) {
            int ix = px - 1 + dx;
            if ((unsigned)ix >= PP) continue;
            acc += dww[c * 9 + dy * 3 + dx] *
                   g_xpool[((size_t)b * NPOS + iy * PP + ix) * DIM + c];
        }
    }
    acc = (acc - mean[c]) * (gamma[c] * rsqrtf(var[c] + 1e-5f)) + beta[c];
    acc = 0.5f * acc * (1.f + erff(acc * 0.70710678118654752f));
    g_vmid[((size_t)b * NPOS + p) * DIM + c] = roundtf(acc);
}

// ---------------- mma tf32 GEMM: C[M,N] = A[M,K] * B[N,K]^T + bias ---------
// Inputs A,B pre-rounded to tf32 (valid tf32 bit patterns -> no in-loop cvt).
// block tile 128x64, 256 threads (8 warps, 4x2), K-chunk 32, double-buffered.
__global__ __launch_bounds__(256) void gemm_mma_kernel(
        const float* __restrict__ A, const float* __restrict__ B,
        const float* __restrict__ bias, float* __restrict__ C,
        int M, int N, int K, int round_out) {
    __shared__ uint2 Ap[2][4][128][4];   // [buf][kgroup][row][tig] = (k, k+4)
    __shared__ uint2 Bp[2][4][64][4];
    int tid = threadIdx.x;
    int lane = tid & 31, w = tid >> 5, g = lane >> 2, tig = lane & 3;
    int wm = w >> 1, wn = w & 1;
    int m0 = blockIdx.y * 128, n0 = blockIdx.x * 64;
    float c[2][4][4] = {};

    int nchunks = K >> 5;
    int ar[4], ac4[4], br[2], bc4[2];
    float4 ra[4], rb[2];
#pragma unroll
    for (int i = 0; i < 4; i++) { int id = tid + i * 256; ar[i] = id >> 3; ac4[i] = id & 7; }
#pragma unroll
    for (int i = 0; i < 2; i++) { int id = tid + i * 256; br[i] = id >> 3; bc4[i] = id & 7; }

#pragma unroll
    for (int i = 0; i < 4; i++)
        ra[i] = *(const float4*)&A[(size_t)(m0 + ar[i]) * K + ac4[i] * 4];
#pragma unroll
    for (int i = 0; i < 2; i++)
        rb[i] = *(const float4*)&B[(size_t)(n0 + br[i]) * K + bc4[i] * 4];

    // store chunk 0 into buf 0
#pragma unroll
    for (int i = 0; i < 4; i++) {
        int kg = ac4[i] >> 1, half = ac4[i] & 1;
        uint32_t* dst = (uint32_t*)&Ap[0][kg][ar[i]][0];
        dst[0 + half] = __float_as_uint(ra[i].x); dst[2 + half] = __float_as_uint(ra[i].y);
        dst[4 + half] = __float_as_uint(ra[i].z); dst[6 + half] = __float_as_uint(ra[i].w);
    }
#pragma unroll
    for (int i = 0; i < 2; i++) {
        int kg = bc4[i] >> 1, half = bc4[i] & 1;
        uint32_t* dst = (uint32_t*)&Bp[0][kg][br[i]][0];
        dst[0 + half] = __float_as_uint(rb[i].x); dst[2 + half] = __float_as_uint(rb[i].y);
        dst[4 + half] = __float_as_uint(rb[i].z); dst[6 + half] = __float_as_uint(rb[i].w);
    }
    __syncthreads();

    for (int kc = 0; kc < nchunks; kc++) {
        int cur = kc & 1;
        if (kc + 1 < nchunks) {
            int ko = (kc + 1) * 32;
#pragma unroll
            for (int i = 0; i < 4; i++)
                ra[i] = *(const float4*)&A[(size_t)(m0 + ar[i]) * K + ko + ac4[i] * 4];
#pragma unroll
            for (int i = 0; i < 2; i++)
                rb[i] = *(const float4*)&B[(size_t)(n0 + br[i]) * K + ko + bc4[i] * 4];
        }
#pragma unroll
        for (int ks = 0; ks < 4; ks++) {
            uint2 aL0 = Ap[cur][ks][wm * 32 + g][tig];
            uint2 aH0 = Ap[cur][ks][wm * 32 + 8 + g][tig];
            uint2 aL1 = Ap[cur][ks][wm * 32 + 16 + g][tig];
            uint2 aH1 = Ap[cur][ks][wm * 32 + 24 + g][tig];
#pragma unroll
            for (int nt = 0; nt < 4; nt++) {
                uint2 bb = Bp[cur][ks][wn * 32 + nt * 8 + g][tig];
                mma4(c[0][nt], aL0.x, aH0.x, aL0.y, aH0.y, bb.x, bb.y);
                mma4(c[1][nt], aL1.x, aH1.x, aL1.y, aH1.y, bb.x, bb.y);
            }
        }
        if (kc + 1 < nchunks) {
            int nxt = cur ^ 1;
#pragma unroll
            for (int i = 0; i < 4; i++) {
                int kg = ac4[i] >> 1, half = ac4[i] & 1;
                uint32_t* dst = (uint32_t*)&Ap[nxt][kg][ar[i]][0];
                dst[0 + half] = __float_as_uint(ra[i].x); dst[2 + half] = __float_as_uint(ra[i].y);
                dst[4 + half] = __float_as_uint(ra[i].z); dst[6 + half] = __float_as_uint(ra[i].w);
            }
#pragma unroll
            for (int i = 0; i < 2; i++) {
                int kg = bc4[i] >> 1, half = bc4[i] & 1;
                uint32_t* dst = (uint32_t*)&Bp[nxt][kg][br[i]][0];
                dst[0 + half] = __float_as_uint(rb[i].x); dst[2 + half] = __float_as_uint(rb[i].y);
                dst[4 + half] = __float_as_uint(rb[i].z); dst[6 + half] = __float_as_uint(rb[i].w);
            }
            __syncthreads();
        }
    }
#pragma unroll
    for (int mt = 0; mt < 2; mt++) {
        int r = m0 + wm * 32 + mt * 16 + g;
#pragma unroll
        for (int nt = 0; nt < 4; nt++) {
            int n = n0 + wn * 32 + nt * 8 + 2 * tig;
            float bx = bias[n], by = bias[n + 1];
            float o0 = c[mt][nt][0] + bx, o1 = c[mt][nt][1] + by;
            float o2 = c[mt][nt][2] + bx, o3 = c[mt][nt][3] + by;
            if (round_out) {
                o0 = roundtf(o0); o1 = roundtf(o1); o2 = roundtf(o2); o3 = roundtf(o3);
            }
            *(float2*)&C[(size_t)r * N + n] = make_float2(o0, o1);
            *(float2*)&C[(size_t)(r + 8) * N + n] = make_float2(o2, o3);
        }
    }
}

// ---------------- 5) attention per (b,h) via tf32 mma, 25 warps ------------
// scores computed analytically into A fragments; V (pre-rounded) in smem;
// softmax shift m_i = |qx|max|kx| + |qy|max|ky| (exact-safe, no max pass).
__global__ __launch_bounds__(800, 1) void attn_mma_kernel() {
    extern __shared__ float smem[];
    uint2* Vp = (uint2*)smem;                      // [98][64][4] pairs (k, k+4): 200704 B
    float* kx_s = smem + (98 * 64 * 4 * 2);        // 784 floats
    float* ky_s = kx_s + NPOS;
    __shared__ float red[64];
    int h = blockIdx.x, b = blockIdx.y;
    int tid = threadIdx.x, lane = tid & 31, w = tid >> 5;
    int g = lane >> 2, tig = lane & 3;
    const int NT = 800, NW = 25;

    const float* vsrc = g_v + (size_t)b * NPOS * INNER + h * DH;
    for (int i = tid; i < NPOS * DH; i += NT) {
        int j = i >> 6, n = i & 63;
        uint32_t tv = __float_as_uint(vsrc[(size_t)j * INNER + n]);  // pre-rounded
        int jg = j >> 3, kk = j & 7;
        uint32_t* cell = (uint32_t*)&Vp[(jg * 64 + n) * 4 + (kk & 3)];
        cell[kk >> 2] = tv;
    }
    const float* ksrc = g_k + ((size_t)b * HEADS + h) * NPOS * 2;
    float axm = 0.f, aym = 0.f;
    for (int i = tid; i < NPOS; i += NT) {
        float2 kv = ((const float2*)ksrc)[i];
        float kx = kv.x * 0.125f, ky = kv.y * 0.125f;
        kx_s[i] = kx; ky_s[i] = ky;
        axm = fmaxf(axm, fabsf(kx)); aym = fmaxf(aym, fabsf(ky));
    }
#pragma unroll
    for (int o = 16; o > 0; o >>= 1) {
        axm = fmaxf(axm, __shfl_xor_sync(0xffffffffu, axm, o));
        aym = fmaxf(aym, __shfl_xor_sync(0xffffffffu, aym, o));
    }
    if (lane == 0) { red[w] = axm; red[32 + w] = aym; }
    __syncthreads();
    float Mx = red[0], My = red[32];
#pragma unroll
    for (int i = 1; i < NW; i++) { Mx = fmaxf(Mx, red[i]); My = fmaxf(My, red[32 + i]); }

    const float2* qsrc = (const float2*)(g_q + ((size_t)b * HEADS + h) * NPOS * 2);
    float* odst = g_ao + (size_t)b * NPOS * INNER + h * DH;

    for (int t = w; t < 49; t += NW) {
        int r0 = t * 16 + g, r1 = r0 + 8;
        float2 q0 = qsrc[r0], q1 = qsrc[r1];
        float m0v = fabsf(q0.x) * Mx + fabsf(q0.y) * My;
        float m1v = fabsf(q1.x) * Mx + fabsf(q1.y) * My;
        float c[8][4];
#pragma unroll
        for (int nt = 0; nt < 8; nt++)
#pragma unroll
            for (int e = 0; e < 4; e++) c[nt][e] = 0.f;
        float la = 0.f, lb = 0.f;
        for (int jg = 0; jg < 98; jg++) {
            int ja = jg * 8 + tig, jb2 = ja + 4;
            float kxa = kx_s[ja], kya = ky_s[ja];
            float kxb = kx_s[jb2], kyb = ky_s[jb2];
            float p0 = __expf(fmaf(q0.x, kxa, q0.y * kya) - m0v);
            float p1 = __expf(fmaf(q1.x, kxa, q1.y * kya) - m1v);
            float p2 = __expf(fmaf(q0.x, kxb, q0.y * kyb) - m0v);
            float p3 = __expf(fmaf(q1.x, kxb, q1.y * kyb) - m1v);
            uint32_t a0 = f2tf(p0), a1 = f2tf(p1), a2 = f2tf(p2), a3 = f2tf(p3);
            la += __uint_as_float(a0) + __uint_as_float(a2);
            lb += __uint_as_float(a1) + __uint_as_float(a3);
            const uint2* vrow = &Vp[(size_t)jg * 256 + tig];
#pragma unroll
            for (int nt = 0; nt < 8; nt++) {
                uint2 bb = vrow[(nt * 8 + g) * 4];
                mma4(c[nt], a0, a1, a2, a3, bb.x, bb.y);
            }
        }
        la += __shfl_xor_sync(0xffffffffu, la, 1);
        la += __shfl_xor_sync(0xffffffffu, la, 2);
        lb += __shfl_xor_sync(0xffffffffu, lb, 1);
        lb += __shfl_xor_sync(0xffffffffu, lb, 2);
        float i0 = 1.f / la, i1 = 1.f / lb;
#pragma unroll
        for (int nt = 0; nt < 8; nt++) {
            *(float2*)&odst[(size_t)r0 * INNER + nt * 8 + 2 * tig] =
                make_float2(roundtf(c[nt][0] * i0), roundtf(c[nt][1] * i0));
            *(float2*)&odst[(size_t)r1 * INNER + nt * 8 + 2 * tig] =
                make_float2(roundtf(c[nt][2] * i1), roundtf(c[nt][3] * i1));
        }
    }
}

// ---------------- 7) bicubic x2 upsample (align_corners=False, a=-0.75) ----
__global__ void upsample_kernel(float* __restrict__ out) {
    extern __shared__ float rows[];   // [4][28][256]
    int oy = blockIdx.x, b = blockIdx.y, c = threadIdx.x;
    int iy0; const float* wy;
    if (oy & 1) { iy0 = (oy - 1) >> 1; wy = c_W25; }
    else        { iy0 = (oy >> 1) - 1; wy = c_W75; }
#pragma unroll
    for (int r = 0; r < 4; r++) {
        int sy = min(max(iy0 - 1 + r, 0), PP - 1);
        const float* src = &g_y28[((size_t)b * NPOS + sy * PP) * DIM];
        for (int i = c; i < PP * DIM; i += 256) rows[r * PP * DIM + i] = src[i];
    }
    __syncthreads();
    for (int ox = 0; ox < IMG; ox++) {
        int ix0; const float* wx;
        if (ox & 1) { ix0 = (ox - 1) >> 1; wx = c_W25; }
        else        { ix0 = (ox >> 1) - 1; wx = c_W75; }
        int sx0 = min(max(ix0 - 1, 0), PP - 1);
        int sx1 = min(max(ix0 + 0, 0), PP - 1);
        int sx2 = min(max(ix0 + 1, 0), PP - 1);
        int sx3 = min(max(ix0 + 2, 0), PP - 1);
        float acc = 0.f;
#pragma unroll
        for (int r = 0; r < 4; r++) {
            const float* rp = &rows[r * PP * DIM];
            float hsum = wx[0] * rp[sx0 * DIM + c]
                       + wx[1] * rp[sx1 * DIM + c]
                       + wx[2] * rp[sx2 * DIM + c]
                       + wx[3] * rp[sx3 * DIM + c];
            acc = fmaf(wy[r], hsum, acc);
        }
        out[((size_t)b * IMG * IMG + oy * IMG + ox) * DIM + c] = acc;
    }
}

// ---------------- launch ---------------------------------------------------
extern "C" void kernel_launch(void* const* d_in, const int* in_sizes, int n_in,
                              void* d_out, int out_size) {
    const float* x     = (const float*)d_in[0];
    const float* q_w   = (const float*)d_in[1];
    const float* q_b   = (const float*)d_in[2];
    const float* k_w   = (const float*)d_in[3];
    const float* k_b   = (const float*)d_in[4];
    const float* dw_w  = (const float*)d_in[5];
    const float* dw_b  = (const float*)d_in[6];
    const float* bn_g  = (const float*)d_in[7];
    const float* bn_b  = (const float*)d_in[8];
    const float* bn_m  = (const float*)d_in[9];
    const float* bn_v  = (const float*)d_in[10];
    const float* pw_w  = (const float*)d_in[11];
    const float* pw_b  = (const float*)d_in[12];
    const float* out_w = (const float*)d_in[13];
    const float* out_b = (const float*)d_in[14];
    float* out = (float*)d_out;

    const int ATTN_SMEM = 98 * 64 * 4 * 8 + 2 * NPOS * 4;            // 206976
    const int UPS_SMEM  = 4 * PP * DIM * (int)sizeof(float);         // 114688
    cudaFuncSetAttribute(attn_mma_kernel, cudaFuncAttributeMaxDynamicSharedMemorySize, ATTN_SMEM);
    cudaFuncSetAttribute(upsample_kernel, cudaFuncAttributeMaxDynamicSharedMemorySize, UPS_SMEM);

    void *p_vmid, *p_v, *p_ao, *p_y28, *p_pww, *p_oww;
    cudaGetSymbolAddress(&p_vmid, g_vmid);
    cudaGetSymbolAddress(&p_v, g_v);
    cudaGetSymbolAddress(&p_ao, g_ao);
    cudaGetSymbolAddress(&p_y28, g_y28);
    cudaGetSymbolAddress(&p_pww, g_pww);
    cudaGetSymbolAddress(&p_oww, g_oww);

    round_weights_kernel<<<(INNER * DIM + 255) / 256, 256>>>(pw_w, out_w);
    pool_stats_kernel<<<dim3(NPOS, BATCH), 256>>>(x);
    qk_conv_kernel<<<dim3(NPOS, BATCH), 32>>>(q_w, q_b, k_w, k_b);
    dw_bn_gelu_kernel<<<dim3(NPOS, BATCH), 256>>>(dw_w, dw_b, bn_g, bn_b, bn_m, bn_v);
    // pointwise conv: [12544,256] x [512,256]^T -> [12544,512] (tf32-rounded out)
    gemm_mma_kernel<<<dim3(INNER / 64, (BATCH * NPOS) / 128), 256>>>(
        (const float*)p_vmid, (const float*)p_pww, pw_b, (float*)p_v,
        BATCH * NPOS, INNER, DIM, 1);
    attn_mma_kernel<<<dim3(HEADS, BATCH), 800, ATTN_SMEM>>>();
    // output projection: [12544,512] x [256,512]^T -> [12544,256]
    gemm_mma_kernel<<<dim3(DIM / 64, (BATCH * NPOS) / 128), 256>>>(
        (const float*)p_ao, (const float*)p_oww, out_b, (float*)p_y28,
        BATCH * NPOS, DIM, INNER, 0);
    upsample_kernel<<<dim3(IMG, BATCH), 256, UPS_SMEM>>>(out);
}

// round 5
// speedup vs baseline: 4.2449x; 1.6546x over previous
#include <cuda_runtime.h>
#include <cuda_fp16.h>
#include <math.h>
#include <stdint.h>

#define BATCH 16
#define IMG 56
#define PP 28
#define NPOS 784
#define DIM 256
#define HEADS 8
#define DH 64
#define INNER 512

// ---------------- scratch (static device allocations; no cudaMalloc) -------
__device__ float  g_xpool[BATCH * NPOS * DIM];    // pooled fp32 [b, p, c]
__device__ float  g_attn2[BATCH * NPOS * 2];      // mean/max over channels
__device__ float  g_q[BATCH * HEADS * NPOS * 2];
__device__ float  g_k[BATCH * HEADS * NPOS * 2];
__device__ __half g_vmid_h[BATCH * NPOS * DIM];   // after dw+BN+GELU (fp16)
__device__ __half g_v_h[BATCH * NPOS * INNER];    // after pointwise conv (fp16)
__device__ __half g_ao_h[BATCH * NPOS * INNER];   // attention out (fp16)
__device__ float  g_y28[BATCH * NPOS * DIM];      // after out-proj (fp32)
__device__ __half g_pww_h[INNER * DIM];           // fp16 pw_w
__device__ __half g_oww_h[DIM * INNER];           // fp16 out_w

// bicubic (a=-0.75) weights for t=0.25 and t=0.75 (half-pixel, x2)
__constant__ float c_W25[4] = {-0.10546875f, 0.87890625f, 0.26171875f, -0.03515625f};
__constant__ float c_W75[4] = {-0.03515625f, 0.26171875f, 0.87890625f, -0.10546875f};

// ---------------- fp16 helpers ---------------------------------------------
__device__ __forceinline__ uint32_t pack_h2(float lo, float hi) {
    uint32_t r;
    asm("cvt.rn.f16x2.f32 %0, %1, %2;" : "=r"(r) : "f"(hi), "f"(lo));
    return r;
}

__device__ __forceinline__ void mma_h(float c[4], uint32_t a0, uint32_t a1,
                                      uint32_t a2, uint32_t a3,
                                      uint32_t b0, uint32_t b1) {
    asm volatile(
        "mma.sync.aligned.m16n8k16.row.col.f32.f16.f16.f32 "
        "{%0,%1,%2,%3},{%4,%5,%6,%7},{%8,%9},{%0,%1,%2,%3};"
        : "+f"(c[0]), "+f"(c[1]), "+f"(c[2]), "+f"(c[3])
        : "r"(a0), "r"(a1), "r"(a2), "r"(a3), "r"(b0), "r"(b1));
}

// ---------------- 0) convert weights to fp16 once --------------------------
__global__ void round_weights_kernel(const float* __restrict__ pw,
                                     const float* __restrict__ ow) {
    int i = blockIdx.x * 256 + threadIdx.x;
    if (i < INNER * DIM) {
        g_pww_h[i] = __float2half(pw[i]);
        g_oww_h[i] = __float2half(ow[i]);
    }
}

// ---------------- 1) avgpool(3,2,1) + channel mean/max (row-sliding) -------
__global__ void pool_row_kernel(const float* __restrict__ x) {
    __shared__ float srow[PP][DIM];
    int py = blockIdx.x, b = blockIdx.y, c = threadIdx.x;
    int lane = c & 31, w = c >> 5;
    const float* base = x + (size_t)b * IMG * IMG * DIM + c;
    int rm = 2 * py - 1, r0 = 2 * py, rp = 2 * py + 1;  // rm may be -1 (py=0)
    bool vm = rm >= 0;
    float* outp = g_xpool + ((size_t)b * NPOS + py * PP) * DIM + c;

    float cprev = 0.f;  // colsum at ix=-1
#pragma unroll 4
    for (int px = 0; px < PP; px++) {
        int ix0 = 2 * px, ix1 = 2 * px + 1;
        float c0 = base[(size_t)(r0 * IMG + ix0) * DIM] + base[(size_t)(rp * IMG + ix0) * DIM];
        float c1 = base[(size_t)(r0 * IMG + ix1) * DIM] + base[(size_t)(rp * IMG + ix1) * DIM];
        if (vm) {
            c0 += base[(size_t)(rm * IMG + ix0) * DIM];
            c1 += base[(size_t)(rm * IMG + ix1) * DIM];
        }
        float pool = (cprev + c0 + c1) * (1.f / 9.f);
        cprev = c1;
        outp[(size_t)px * DIM] = pool;
        srow[px][c] = pool;
    }
    __syncthreads();
    // stats: warp w handles px = w, w+8, w+16, w+24
    for (int px = w; px < PP; px += 8) {
        float s = 0.f, m = -1e30f;
#pragma unroll
        for (int k = 0; k < 8; k++) {
            float v = srow[px][lane + 32 * k];
            s += v; m = fmaxf(m, v);
        }
#pragma unroll
        for (int o = 16; o > 0; o >>= 1) {
            s += __shfl_down_sync(0xffffffffu, s, o);
            m = fmaxf(m, __shfl_down_sync(0xffffffffu, m, o));
        }
        if (lane == 0) {
            g_attn2[((size_t)b * NPOS + py * PP + px) * 2 + 0] = s * (1.f / DIM);
            g_attn2[((size_t)b * NPOS + py * PP + px) * 2 + 1] = m;
        }
    }
}

// ---------------- 2) q/k 3x3 convs on the 2-channel attention map ----------
__global__ void qk_conv_kernel(const float* __restrict__ qw, const float* __restrict__ qb,
                               const float* __restrict__ kw, const float* __restrict__ kb) {
    int p = blockIdx.x, b = blockIdx.y, t = threadIdx.x;
    int sel = t >> 4, och = t & 15;
    const float* w = sel ? kw : qw;
    const float* bi = sel ? kb : qb;
    float* outp = sel ? g_k : g_q;
    int py = p / PP, px = p % PP;
    float acc = bi[och];
#pragma unroll
    for (int dy = 0; dy < 3; dy++) {
        int iy = py - 1 + dy;
        if ((unsigned)iy >= PP) continue;
#pragma unroll
        for (int dx = 0; dx < 3; dx++) {
            int ix = px - 1 + dx;
            if ((unsigned)ix >= PP) continue;
            const float* a2 = &g_attn2[((size_t)b * NPOS + iy * PP + ix) * 2];
            acc += w[((och * 2 + 0) * 3 + dy) * 3 + dx] * a2[0]
                 + w[((och * 2 + 1) * 3 + dy) * 3 + dx] * a2[1];
        }
    }
    int h = och >> 1, comp = och & 1;
    outp[(((size_t)b * HEADS + h) * NPOS + p) * 2 + comp] = acc;
}

// ---------------- 3) depthwise 3x3 + BN + GELU (row-sliding, fp16 out) -----
__global__ void dw_row_kernel(const float* __restrict__ dww, const float* __restrict__ dwb,
                              const float* __restrict__ gamma, const float* __restrict__ beta,
                              const float* __restrict__ mean, const float* __restrict__ var) {
    int py = blockIdx.x, b = blockIdx.y, c = threadIdx.x;
    float wgt[9];
#pragma unroll
    for (int k = 0; k < 9; k++) wgt[k] = dww[c * 9 + k];
    float bias = dwb[c];
    float sc = gamma[c] * rsqrtf(var[c] + 1e-5f);
    float bm = mean[c], bb = beta[c];

    bool vu = py > 0, vd = py < PP - 1;
    const float* rowu = g_xpool + ((size_t)b * NPOS + (py - 1) * PP) * DIM + c;
    const float* rowm = g_xpool + ((size_t)b * NPOS + py * PP) * DIM + c;
    const float* rowd = g_xpool + ((size_t)b * NPOS + (py + 1) * PP) * DIM + c;
    __half* outp = g_vmid_h + ((size_t)b * NPOS + py * PP) * DIM + c;

    float pu = 0.f, pm = 0.f, pd = 0.f;  // col px-1
    float cu = vu ? rowu[0] : 0.f;
    float cm = rowm[0];
    float cd = vd ? rowd[0] : 0.f;
#pragma unroll 4
    for (int px = 0; px < PP; px++) {
        float nu = 0.f, nm = 0.f, nd = 0.f;
        if (px < PP - 1) {
            size_t o = (size_t)(px + 1) * DIM;
            nu = vu ? rowu[o] : 0.f;
            nm = rowm[o];
            nd = vd ? rowd[o] : 0.f;
        }
        float acc = bias;
        acc = fmaf(wgt[0], pu, acc); acc = fmaf(wgt[1], cu, acc); acc = fmaf(wgt[2], nu, acc);
        acc = fmaf(wgt[3], pm, acc); acc = fmaf(wgt[4], cm, acc); acc = fmaf(wgt[5], nm, acc);
        acc = fmaf(wgt[6], pd, acc); acc = fmaf(wgt[7], cd, acc); acc = fmaf(wgt[8], nd, acc);
        acc = (acc - bm) * sc + bb;
        acc = 0.5f * acc * (1.f + erff(acc * 0.70710678118654752f));
        outp[(size_t)px * DIM] = __float2half(acc);
        pu = cu; pm = cm; pd = cd;
        cu = nu; cm = nm; cd = nd;
    }
}

// ---------------- fp16 mma GEMM: C[M,N] = A[M,K]*B[N,K]^T + bias -----------
// 128x64 tile, 256 threads (8 warps 4x2), K-chunk 32, double-buffered.
__global__ __launch_bounds__(256) void gemm_h_kernel(
        const __half* __restrict__ A, const __half* __restrict__ B,
        const float* __restrict__ bias, void* __restrict__ Cv,
        int M, int N, int K, int out_half) {
    __shared__ uint2 As2[2][2][128][4];   // [buf][kg][row][tig]: .x=k pair 2tig, .y=pair 2tig+8
    __shared__ uint2 Bs2[2][2][64][4];
    int tid = threadIdx.x;
    int lane = tid & 31, w = tid >> 5, g = lane >> 2, tig = lane & 3;
    int wm = w >> 1, wn = w & 1;
    int m0 = blockIdx.y * 128, n0 = blockIdx.x * 64;
    float c[2][4][4] = {};

    int nchunks = K >> 5;
    // A: 2 uint4 per thread per chunk; B: 1
    int arow[2], aq[2];
#pragma unroll
    for (int i = 0; i < 2; i++) { int s = tid + i * 256; arow[i] = s >> 2; aq[i] = s & 3; }
    int brow = tid >> 2, bq = tid & 3;
    uint4 ra[2], rb;

#pragma unroll
    for (int i = 0; i < 2; i++)
        ra[i] = *(const uint4*)&A[(size_t)(m0 + arow[i]) * K + aq[i] * 8];
    rb = *(const uint4*)&B[(size_t)(n0 + brow) * K + bq * 8];

#pragma unroll
    for (int i = 0; i < 2; i++) {
        uint32_t* p = (uint32_t*)&As2[0][aq[i] >> 1][arow[i]][0] + (aq[i] & 1);
        p[0] = ra[i].x; p[2] = ra[i].y; p[4] = ra[i].z; p[6] = ra[i].w;
    }
    {
        uint32_t* p = (uint32_t*)&Bs2[0][bq >> 1][brow][0] + (bq & 1);
        p[0] = rb.x; p[2] = rb.y; p[4] = rb.z; p[6] = rb.w;
    }
    __syncthreads();

    for (int kc = 0; kc < nchunks; kc++) {
        int cur = kc & 1;
        if (kc + 1 < nchunks) {
            int ko = (kc + 1) * 32;
#pragma unroll
            for (int i = 0; i < 2; i++)
                ra[i] = *(const uint4*)&A[(size_t)(m0 + arow[i]) * K + ko + aq[i] * 8];
            rb = *(const uint4*)&B[(size_t)(n0 + brow) * K + ko + bq * 8];
        }
#pragma unroll
        for (int kg = 0; kg < 2; kg++) {
            uint2 a00 = As2[cur][kg][wm * 32 + g][tig];
            uint2 a08 = As2[cur][kg][wm * 32 + 8 + g][tig];
            uint2 a16 = As2[cur][kg][wm * 32 + 16 + g][tig];
            uint2 a24 = As2[cur][kg][wm * 32 + 24 + g][tig];
#pragma unroll
            for (int nt = 0; nt < 4; nt++) {
                uint2 bb = Bs2[cur][kg][wn * 32 + nt * 8 + g][tig];
                mma_h(c[0][nt], a00.x, a08.x, a00.y, a08.y, bb.x, bb.y);
                mma_h(c[1][nt], a16.x, a24.x, a16.y, a24.y, bb.x, bb.y);
            }
        }
        if (kc + 1 < nchunks) {
            int nxt = cur ^ 1;
#pragma unroll
            for (int i = 0; i < 2; i++) {
                uint32_t* p = (uint32_t*)&As2[nxt][aq[i] >> 1][arow[i]][0] + (aq[i] & 1);
                p[0] = ra[i].x; p[2] = ra[i].y; p[4] = ra[i].z; p[6] = ra[i].w;
            }
            uint32_t* p = (uint32_t*)&Bs2[nxt][bq >> 1][brow][0] + (bq & 1);
            p[0] = rb.x; p[2] = rb.y; p[4] = rb.z; p[6] = rb.w;
            __syncthreads();
        }
    }
#pragma unroll
    for (int mt = 0; mt < 2; mt++) {
        int r = m0 + wm * 32 + mt * 16 + g;
#pragma unroll
        for (int nt = 0; nt < 4; nt++) {
            int n = n0 + wn * 32 + nt * 8 + 2 * tig;
            float bx = bias[n], by = bias[n + 1];
            float o0 = c[mt][nt][0] + bx, o1 = c[mt][nt][1] + by;
            float o2 = c[mt][nt][2] + bx, o3 = c[mt][nt][3] + by;
            if (out_half) {
                __half* C = (__half*)Cv;
                *(uint32_t*)&C[(size_t)r * N + n] = pack_h2(o0, o1);
                *(uint32_t*)&C[(size_t)(r + 8) * N + n] = pack_h2(o2, o3);
            } else {
                float* C = (float*)Cv;
                *(float2*)&C[(size_t)r * N + n] = make_float2(o0, o1);
                *(float2*)&C[(size_t)(r + 8) * N + n] = make_float2(o2, o3);
            }
        }
    }
}

// ---------------- 5) attention per (b,h) via fp16 m16n8k16 -----------------
// scores tiny (|s|<~1): softmax shift cancels exactly -> p = exp(s), no max pass.
__global__ __launch_bounds__(800, 1) void attn_h_kernel() {
    extern __shared__ char smc[];
    uint2* Vp = (uint2*)smc;                       // [49][64][4] : 100352 B
    float2* kxy = (float2*)(smc + 49 * 64 * 4 * 8);  // 784 float2 : 6272 B
    int h = blockIdx.x, b = blockIdx.y;
    int tid = threadIdx.x, lane = tid & 31, w = tid >> 5;
    int g = lane >> 2, tig = lane & 3;

    // pack V (fp16) into B-fragment layout: cell[(jg*64+n)*4+tig] = {pair j=2tig, pair j=2tig+8}
    const __half* vsrc = g_v_h + (size_t)b * NPOS * INNER + h * DH;
    for (int i = tid; i < 392 * 32; i += 800) {
        int jp = i >> 5, n2 = (i & 31) * 2;
        uint32_t a = *(const uint32_t*)&vsrc[(size_t)(2 * jp) * INNER + n2];
        uint32_t bu = *(const uint32_t*)&vsrc[(size_t)(2 * jp + 1) * INNER + n2];
        uint32_t o0 = __byte_perm(a, bu, 0x5410);  // (V[2jp][n2], V[2jp+1][n2])
        uint32_t o1 = __byte_perm(a, bu, 0x7632);  // (V[2jp][n2+1], V[2jp+1][n2+1])
        int jg = jp >> 3, lp = jp & 7;
        int t4 = lp & 3, hf = lp >> 2;
        ((uint32_t*)&Vp[(jg * 64 + n2) * 4 + t4])[hf] = o0;
        ((uint32_t*)&Vp[(jg * 64 + n2 + 1) * 4 + t4])[hf] = o1;
    }
    const float* ksrc = g_k + ((size_t)b * HEADS + h) * NPOS * 2;
    for (int i = tid; i < NPOS; i += 800) {
        float2 kv = ((const float2*)ksrc)[i];
        kxy[i] = make_float2(kv.x * 0.125f, kv.y * 0.125f);
    }
    __syncthreads();

    const float2* qsrc = (const float2*)(g_q + ((size_t)b * HEADS + h) * NPOS * 2);
    __half* odst = g_ao_h + (size_t)b * NPOS * INNER + h * DH;

    for (int t = w; t < 49; t += 25) {
        int r0 = t * 16 + g, r1 = r0 + 8;
        float2 q0 = qsrc[r0], q1 = qsrc[r1];
        float c[8][4];
#pragma unroll
        for (int nt = 0; nt < 8; nt++)
#pragma unroll
            for (int e = 0; e < 4; e++) c[nt][e] = 0.f;
        float la = 0.f, lb = 0.f;
        for (int jg = 0; jg < 49; jg++) {
            int jbase = jg * 16;
            float4 kk0 = *(const float4*)&kxy[jbase + 2 * tig];      // j=2tig: (kx,ky), j+1
            float4 kk1 = *(const float4*)&kxy[jbase + 2 * tig + 8];  // j=2tig+8, +9
            float p00 = __expf(fmaf(q0.x, kk0.x, q0.y * kk0.y));
            float p01 = __expf(fmaf(q0.x, kk0.z, q0.y * kk0.w));
            float p02 = __expf(fmaf(q0.x, kk1.x, q0.y * kk1.y));
            float p03 = __expf(fmaf(q0.x, kk1.z, q0.y * kk1.w));
            float p10 = __expf(fmaf(q1.x, kk0.x, q1.y * kk0.y));
            float p11 = __expf(fmaf(q1.x, kk0.z, q1.y * kk0.w));
            float p12 = __expf(fmaf(q1.x, kk1.x, q1.y * kk1.y));
            float p13 = __expf(fmaf(q1.x, kk1.z, q1.y * kk1.w));
            la += (p00 + p01) + (p02 + p03);
            lb += (p10 + p11) + (p12 + p13);
            uint32_t a0 = pack_h2(p00, p01), a1 = pack_h2(p10, p11);
            uint32_t a2 = pack_h2(p02, p03), a3 = pack_h2(p12, p13);
            const uint2* vrow = &Vp[(jg * 64) * 4 + tig];
#pragma unroll
            for (int nt = 0; nt < 8; nt++) {
                uint2 bb = vrow[(nt * 8 + g) * 4];
                mma_h(c[nt], a0, a1, a2, a3, bb.x, bb.y);
            }
        }
        la += __shfl_xor_sync(0xffffffffu, la, 1);
        la += __shfl_xor_sync(0xffffffffu, la, 2);
        lb += __shfl_xor_sync(0xffffffffu, lb, 1);
        lb += __shfl_xor_sync(0xffffffffu, lb, 2);
        float i0 = 1.f / la, i1 = 1.f / lb;
#pragma unroll
        for (int nt = 0; nt < 8; nt++) {
            int n = nt * 8 + 2 * tig;
            *(uint32_t*)&odst[(size_t)r0 * INNER + n] = pack_h2(c[nt][0] * i0, c[nt][1] * i0);
            *(uint32_t*)&odst[(size_t)r1 * INNER + n] = pack_h2(c[nt][2] * i1, c[nt][3] * i1);
        }
    }
}

// ---------------- 7) bicubic x2 upsample, separable two-stage --------------
__global__ void upsample2_kernel(float* __restrict__ out) {
    __shared__ float tmp[PP][DIM];
    int oy = blockIdx.x, b = blockIdx.y, c = threadIdx.x;
    int iy0; const float* wy;
    if (oy & 1) { iy0 = (oy - 1) >> 1; wy = c_W25; }
    else        { iy0 = (oy >> 1) - 1; wy = c_W75; }
    int sy0 = min(max(iy0 - 1, 0), PP - 1);
    int sy1 = min(max(iy0 + 0, 0), PP - 1);
    int sy2 = min(max(iy0 + 1, 0), PP - 1);
    int sy3 = min(max(iy0 + 2, 0), PP - 1);
    const float* basep = g_y28 + (size_t)b * NPOS * DIM + c;
    float w0 = wy[0], w1 = wy[1], w2 = wy[2], w3 = wy[3];
#pragma unroll 4
    for (int ix = 0; ix < PP; ix++) {
        float acc = w0 * basep[(size_t)(sy0 * PP + ix) * DIM]
                  + w1 * basep[(size_t)(sy1 * PP + ix) * DIM]
                  + w2 * basep[(size_t)(sy2 * PP + ix) * DIM]
                  + w3 * basep[(size_t)(sy3 * PP + ix) * DIM];
        tmp[ix][c] = acc;
    }
    __syncthreads();
    float* orow = out + ((size_t)b * IMG * IMG + oy * IMG) * DIM + c;
#pragma unroll 4
    for (int ox = 0; ox < IMG; ox++) {
        int ix0; const float* wx;
        if (ox & 1) { ix0 = (ox - 1) >> 1; wx = c_W25; }
        else        { ix0 = (ox >> 1) - 1; wx = c_W75; }
        int sx0 = min(max(ix0 - 1, 0), PP - 1);
        int sx1 = min(max(ix0 + 0, 0), PP - 1);
        int sx2 = min(max(ix0 + 1, 0), PP - 1);
        int sx3 = min(max(ix0 + 2, 0), PP - 1);
        float acc = wx[0] * tmp[sx0][c] + wx[1] * tmp[sx1][c]
                  + wx[2] * tmp[sx2][c] + wx[3] * tmp[sx3][c];
        orow[(size_t)ox * DIM] = acc;
    }
}

// ---------------- launch ---------------------------------------------------
extern "C" void kernel_launch(void* const* d_in, const int* in_sizes, int n_in,
                              void* d_out, int out_size) {
    const float* x     = (const float*)d_in[0];
    const float* q_w   = (const float*)d_in[1];
    const float* q_b   = (const float*)d_in[2];
    const float* k_w   = (const float*)d_in[3];
    const float* k_b   = (const float*)d_in[4];
    const float* dw_w  = (const float*)d_in[5];
    const float* dw_b  = (const float*)d_in[6];
    const float* bn_g  = (const float*)d_in[7];
    const float* bn_b  = (const float*)d_in[8];
    const float* bn_m  = (const float*)d_in[9];
    const float* bn_v  = (const float*)d_in[10];
    const float* pw_w  = (const float*)d_in[11];
    const float* pw_b  = (const float*)d_in[12];
    const float* out_w = (const float*)d_in[13];
    const float* out_b = (const float*)d_in[14];
    float* out = (float*)d_out;

    const int ATTN_SMEM = 49 * 64 * 4 * 8 + NPOS * 8;  // 100352 + 6272 = 106624
    cudaFuncSetAttribute(attn_h_kernel, cudaFuncAttributeMaxDynamicSharedMemorySize, ATTN_SMEM);

    void *p_vmid, *p_v, *p_ao, *p_y28, *p_pww, *p_oww;
    cudaGetSymbolAddress(&p_vmid, g_vmid_h);
    cudaGetSymbolAddress(&p_v, g_v_h);
    cudaGetSymbolAddress(&p_ao, g_ao_h);
    cudaGetSymbolAddress(&p_y28, g_y28);
    cudaGetSymbolAddress(&p_pww, g_pww_h);
    cudaGetSymbolAddress(&p_oww, g_oww_h);

    round_weights_kernel<<<(INNER * DIM + 255) / 256, 256>>>(pw_w, out_w);
    pool_row_kernel<<<dim3(PP, BATCH), 256>>>(x);
    qk_conv_kernel<<<dim3(NPOS, BATCH), 32>>>(q_w, q_b, k_w, k_b);
    dw_row_kernel<<<dim3(PP, BATCH), 256>>>(dw_w, dw_b, bn_g, bn_b, bn_m, bn_v);
    // pointwise conv: [12544,256] x [512,256]^T -> fp16 [12544,512]
    gemm_h_kernel<<<dim3(INNER / 64, (BATCH * NPOS) / 128), 256>>>(
        (const __half*)p_vmid, (const __half*)p_pww, pw_b, p_v,
        BATCH * NPOS, INNER, DIM, 1);
    attn_h_kernel<<<dim3(HEADS, BATCH), 800, ATTN_SMEM>>>();
    // output projection: [12544,512] x [256,512]^T -> fp32 [12544,256]
    gemm_h_kernel<<<dim3(DIM / 64, (BATCH * NPOS) / 128), 256>>>(
        (const __half*)p_ao, (const __half*)p_oww, out_b, p_y28,
        BATCH * NPOS, DIM, INNER, 0);
    upsample2_kernel<<<dim3(IMG, BATCH), 256>>>(out);
}

// round 8
// speedup vs baseline: 4.4302x; 1.0437x over previous
#include <cuda_runtime.h>
#include <cuda_fp16.h>
#include <math.h>
#include <stdint.h>

#define BATCH 16
#define IMG 56
#define PP 28
#define NPOS 784
#define DIM 256
#define HEADS 8
#define DH 64
#define INNER 512

// ---------------- scratch (static device allocations; no cudaMalloc) -------
__device__ float  g_xpool[BATCH * NPOS * DIM];    // pooled fp32 [b, p, c]
__device__ float  g_attn2[BATCH * NPOS * 2];      // mean/max over channels
__device__ float  g_q[BATCH * HEADS * NPOS * 2];
__device__ float  g_k[BATCH * HEADS * NPOS * 2];
__device__ __half g_vmid_h[BATCH * NPOS * DIM];   // after dw+BN+GELU (fp16)
__device__ __half g_v_h[BATCH * NPOS * INNER];    // after pointwise conv (fp16)
__device__ __half g_ao_h[BATCH * NPOS * INNER];   // attention out (fp16)
__device__ float  g_y28[BATCH * NPOS * DIM];      // after out-proj (fp32)
__device__ __half g_pww_h[INNER * DIM];           // fp16 pw_w
__device__ __half g_oww_h[DIM * INNER];           // fp16 out_w

// bicubic (a=-0.75) weights for t=0.25 and t=0.75 (half-pixel, x2)
__constant__ float c_W25[4] = {-0.10546875f, 0.87890625f, 0.26171875f, -0.03515625f};
__constant__ float c_W75[4] = {-0.03515625f, 0.26171875f, 0.87890625f, -0.10546875f};

// ---------------- fp16 helpers ---------------------------------------------
__device__ __forceinline__ uint32_t pack_h2(float lo, float hi) {
    uint32_t r;
    asm("cvt.rn.f16x2.f32 %0, %1, %2;" : "=r"(r) : "f"(hi), "f"(lo));
    return r;
}

__device__ __forceinline__ void mma_h(float c[4], uint32_t a0, uint32_t a1,
                                      uint32_t a2, uint32_t a3,
                                      uint32_t b0, uint32_t b1) {
    asm volatile(
        "mma.sync.aligned.m16n8k16.row.col.f32.f16.f16.f32 "
        "{%0,%1,%2,%3},{%4,%5,%6,%7},{%8,%9},{%0,%1,%2,%3};"
        : "+f"(c[0]), "+f"(c[1]), "+f"(c[2]), "+f"(c[3])
        : "r"(a0), "r"(a1), "r"(a2), "r"(a3), "r"(b0), "r"(b1));
}

// ---------------- 0) convert weights to fp16 once --------------------------
__global__ void round_weights_kernel(const float* __restrict__ pw,
                                     const float* __restrict__ ow) {
    int i = blockIdx.x * 256 + threadIdx.x;
    if (i < INNER * DIM) {
        g_pww_h[i] = __float2half(pw[i]);
        g_oww_h[i] = __float2half(ow[i]);
    }
}

// ---------------- 1) avgpool(3,2,1) + channel mean/max (px-split) ----------
// block = (quarter, py, b): 7 output columns, 256 channels. 45 independent loads.
__global__ void pool_part_kernel(const float* __restrict__ x) {
    __shared__ float srow[7][DIM];
    int quarter = blockIdx.x, py = blockIdx.y, b = blockIdx.z;
    int c = threadIdx.x, lane = c & 31, w = c >> 5;
    int px0 = quarter * 7;
    const float* base = x + (size_t)b * IMG * IMG * DIM + c;
    int rm = 2 * py - 1, r0 = 2 * py, rp = 2 * py + 1;
    bool vm = rm >= 0;

    float cs[15];
#pragma unroll
    for (int i = 0; i < 15; i++) {
        int ix = 2 * px0 - 1 + i;
        if ((unsigned)ix < IMG) {
            float v = base[(size_t)(r0 * IMG + ix) * DIM] + base[(size_t)(rp * IMG + ix) * DIM];
            if (vm) v += base[(size_t)(rm * IMG + ix) * DIM];
            cs[i] = v;
        } else cs[i] = 0.f;
    }
    float* outp = g_xpool + ((size_t)b * NPOS + py * PP + px0) * DIM + c;
#pragma unroll
    for (int i = 0; i < 7; i++) {
        float pool = (cs[2 * i] + cs[2 * i + 1] + cs[2 * i + 2]) * (1.f / 9.f);
        outp[(size_t)i * DIM] = pool;
        srow[i][c] = pool;
    }
    __syncthreads();
    if (w < 7) {
        float s = 0.f, m = -1e30f;
#pragma unroll
        for (int k = 0; k < 8; k++) {
            float v = srow[w][lane + 32 * k];
            s += v; m = fmaxf(m, v);
        }
#pragma unroll
        for (int o = 16; o > 0; o >>= 1) {
            s += __shfl_down_sync(0xffffffffu, s, o);
            m = fmaxf(m, __shfl_down_sync(0xffffffffu, m, o));
        }
        if (lane == 0) {
            g_attn2[((size_t)b * NPOS + py * PP + px0 + w) * 2 + 0] = s * (1.f / DIM);
            g_attn2[((size_t)b * NPOS + py * PP + px0 + w) * 2 + 1] = m;
        }
    }
}

// ---------------- 2) q/k 3x3 convs (8 positions per block) -----------------
__global__ void qk_conv_kernel(const float* __restrict__ qw, const float* __restrict__ qb,
                               const float* __restrict__ kw, const float* __restrict__ kb) {
    int t = threadIdx.x;
    int p = blockIdx.x * 8 + (t >> 5), b = blockIdx.y;
    int tt = t & 31;
    int sel = tt >> 4, och = tt & 15;
    const float* w = sel ? kw : qw;
    const float* bi = sel ? kb : qb;
    float* outp = sel ? g_k : g_q;
    int py = p / PP, px = p % PP;
    float acc = bi[och];
#pragma unroll
    for (int dy = 0; dy < 3; dy++) {
        int iy = py - 1 + dy;
        if ((unsigned)iy >= PP) continue;
#pragma unroll
        for (int dx = 0; dx < 3; dx++) {
            int ix = px - 1 + dx;
            if ((unsigned)ix >= PP) continue;
            const float* a2 = &g_attn2[((size_t)b * NPOS + iy * PP + ix) * 2];
            acc += w[((och * 2 + 0) * 3 + dy) * 3 + dx] * a2[0]
                 + w[((och * 2 + 1) * 3 + dy) * 3 + dx] * a2[1];
        }
    }
    int h = och >> 1, comp = och & 1;
    outp[(((size_t)b * HEADS + h) * NPOS + p) * 2 + comp] = acc;
}

// ---------------- 3) depthwise 3x3 + BN + GELU (px-split, fp16 out) --------
// block = (quarter, py, b): 27 independent loads per thread, 7 outputs.
__global__ void dw_part_kernel(const float* __restrict__ dww, const float* __restrict__ dwb,
                               const float* __restrict__ gamma, const float* __restrict__ beta,
                               const float* __restrict__ mean, const float* __restrict__ var) {
    int quarter = blockIdx.x, py = blockIdx.y, b = blockIdx.z, c = threadIdx.x;
    int px0 = quarter * 7;
    float wgt[9];
#pragma unroll
    for (int k = 0; k < 9; k++) wgt[k] = dww[c * 9 + k];
    float bias = dwb[c];
    float sc = gamma[c] * rsqrtf(var[c] + 1e-5f);
    float bm = mean[c], bb = beta[c];

    const float* basep = g_xpool + (size_t)b * NPOS * DIM + c;
    float vin[3][9];
#pragma unroll
    for (int r = 0; r < 3; r++) {
        int row = py - 1 + r;
        bool vr = (unsigned)row < PP;
#pragma unroll
        for (int cc = 0; cc < 9; cc++) {
            int col = px0 - 1 + cc;
            vin[r][cc] = (vr && (unsigned)col < PP)
                       ? basep[(size_t)(row * PP + col) * DIM] : 0.f;
        }
    }
    __half* outp = g_vmid_h + ((size_t)b * NPOS + py * PP + px0) * DIM + c;
#pragma unroll
    for (int i = 0; i < 7; i++) {
        float acc = bias;
#pragma unroll
        for (int r = 0; r < 3; r++)
#pragma unroll
            for (int d = 0; d < 3; d++)
                acc = fmaf(wgt[r * 3 + d], vin[r][i + d], acc);
        acc = (acc - bm) * sc + bb;
        acc = 0.5f * acc * (1.f + erff(acc * 0.70710678118654752f));
        outp[(size_t)i * DIM] = __float2half(acc);
    }
}

// ---------------- fp16 mma GEMM: C[M,N] = A[M,K]*B[N,K]^T + bias -----------
__global__ __launch_bounds__(256) void gemm_h_kernel(
        const __half* __restrict__ A, const __half* __restrict__ B,
        const float* __restrict__ bias, void* __restrict__ Cv,
        int M, int N, int K, int out_half) {
    __shared__ uint2 As2[2][2][128][4];
    __shared__ uint2 Bs2[2][2][64][4];
    int tid = threadIdx.x;
    int lane = tid & 31, w = tid >> 5, g = lane >> 2, tig = lane & 3;
    int wm = w >> 1, wn = w & 1;
    int m0 = blockIdx.y * 128, n0 = blockIdx.x * 64;
    float c[2][4][4] = {};

    int nchunks = K >> 5;
    int arow[2], aq[2];
#pragma unroll
    for (int i = 0; i < 2; i++) { int s = tid + i * 256; arow[i] = s >> 2; aq[i] = s & 3; }
    int brow = tid >> 2, bq = tid & 3;
    uint4 ra[2], rb;

#pragma unroll
    for (int i = 0; i < 2; i++)
        ra[i] = *(const uint4*)&A[(size_t)(m0 + arow[i]) * K + aq[i] * 8];
    rb = *(const uint4*)&B[(size_t)(n0 + brow) * K + bq * 8];

#pragma unroll
    for (int i = 0; i < 2; i++) {
        uint32_t* p = (uint32_t*)&As2[0][aq[i] >> 1][arow[i]][0] + (aq[i] & 1);
        p[0] = ra[i].x; p[2] = ra[i].y; p[4] = ra[i].z; p[6] = ra[i].w;
    }
    {
        uint32_t* p = (uint32_t*)&Bs2[0][bq >> 1][brow][0] + (bq & 1);
        p[0] = rb.x; p[2] = rb.y; p[4] = rb.z; p[6] = rb.w;
    }
    __syncthreads();

    for (int kc = 0; kc < nchunks; kc++) {
        int cur = kc & 1;
        if (kc + 1 < nchunks) {
            int ko = (kc + 1) * 32;
#pragma unroll
            for (int i = 0; i < 2; i++)
                ra[i] = *(const uint4*)&A[(size_t)(m0 + arow[i]) * K + ko + aq[i] * 8];
            rb = *(const uint4*)&B[(size_t)(n0 + brow) * K + ko + bq * 8];
        }
#pragma unroll
        for (int kg = 0; kg < 2; kg++) {
            uint2 a00 = As2[cur][kg][wm * 32 + g][tig];
            uint2 a08 = As2[cur][kg][wm * 32 + 8 + g][tig];
            uint2 a16 = As2[cur][kg][wm * 32 + 16 + g][tig];
            uint2 a24 = As2[cur][kg][wm * 32 + 24 + g][tig];
#pragma unroll
            for (int nt = 0; nt < 4; nt++) {
                uint2 bb = Bs2[cur][kg][wn * 32 + nt * 8 + g][tig];
                mma_h(c[0][nt], a00.x, a08.x, a00.y, a08.y, bb.x, bb.y);
                mma_h(c[1][nt], a16.x, a24.x, a16.y, a24.y, bb.x, bb.y);
            }
        }
        if (kc + 1 < nchunks) {
            int nxt = cur ^ 1;
#pragma unroll
            for (int i = 0; i < 2; i++) {
                uint32_t* p = (uint32_t*)&As2[nxt][aq[i] >> 1][arow[i]][0] + (aq[i] & 1);
                p[0] = ra[i].x; p[2] = ra[i].y; p[4] = ra[i].z; p[6] = ra[i].w;
            }
            uint32_t* p = (uint32_t*)&Bs2[nxt][bq >> 1][brow][0] + (bq & 1);
            p[0] = rb.x; p[2] = rb.y; p[4] = rb.z; p[6] = rb.w;
            __syncthreads();
        }
    }
#pragma unroll
    for (int mt = 0; mt < 2; mt++) {
        int r = m0 + wm * 32 + mt * 16 + g;
#pragma unroll
        for (int nt = 0; nt < 4; nt++) {
            int n = n0 + wn * 32 + nt * 8 + 2 * tig;
            float bx = bias[n], by = bias[n + 1];
            float o0 = c[mt][nt][0] + bx, o1 = c[mt][nt][1] + by;
            float o2 = c[mt][nt][2] + bx, o3 = c[mt][nt][3] + by;
            if (out_half) {
                __half* C = (__half*)Cv;
                *(uint32_t*)&C[(size_t)r * N + n] = pack_h2(o0, o1);
                *(uint32_t*)&C[(size_t)(r + 8) * N + n] = pack_h2(o2, o3);
            } else {
                float* C = (float*)Cv;
                *(float2*)&C[(size_t)r * N + n] = make_float2(o0, o1);
                *(float2*)&C[(size_t)(r + 8) * N + n] = make_float2(o2, o3);
            }
        }
    }
}

// ---------------- 5) attention per (b,h) via fp16 m16n8k16 -----------------
// scores tiny: softmax shift cancels exactly -> p = exp2(s*log2e), no max pass.
__global__ __launch_bounds__(800, 1) void attn_h_kernel() {
    extern __shared__ char smc[];
    uint2* Vp = (uint2*)smc;                         // [49][64][4] : 100352 B
    float2* kxy = (float2*)(smc + 49 * 64 * 4 * 8);  // 784 float2 : 6272 B
    int h = blockIdx.x, b = blockIdx.y;
    int tid = threadIdx.x, lane = tid & 31, w = tid >> 5;
    int g = lane >> 2, tig = lane & 3;

    const __half* vsrc = g_v_h + (size_t)b * NPOS * INNER + h * DH;
    for (int i = tid; i < 392 * 32; i += 800) {
        int jp = i >> 5, n2 = (i & 31) * 2;
        uint32_t a = *(const uint32_t*)&vsrc[(size_t)(2 * jp) * INNER + n2];
        uint32_t bu = *(const uint32_t*)&vsrc[(size_t)(2 * jp + 1) * INNER + n2];
        uint32_t o0 = __byte_perm(a, bu, 0x5410);
        uint32_t o1 = __byte_perm(a, bu, 0x7632);
        int jg = jp >> 3, lp = jp & 7;
        int t4 = lp & 3, hf = lp >> 2;
        ((uint32_t*)&Vp[(jg * 64 + n2) * 4 + t4])[hf] = o0;
        ((uint32_t*)&Vp[(jg * 64 + n2 + 1) * 4 + t4])[hf] = o1;
    }
    const float* ksrc = g_k + ((size_t)b * HEADS + h) * NPOS * 2;
    const float KSC = 0.125f * 1.4426950408889634f;  // scale * log2(e)
    for (int i = tid; i < NPOS; i += 800) {
        float2 kv = ((const float2*)ksrc)[i];
        kxy[i] = make_float2(kv.x * KSC, kv.y * KSC);
    }
    __syncthreads();

    const float2* qsrc = (const float2*)(g_q + ((size_t)b * HEADS + h) * NPOS * 2);
    __half* odst = g_ao_h + (size_t)b * NPOS * INNER + h * DH;

    for (int t = w; t < 49; t += 25) {
        int r0 = t * 16 + g, r1 = r0 + 8;
        float2 q0 = qsrc[r0], q1 = qsrc[r1];
        float c[8][4];
#pragma unroll
        for (int nt = 0; nt < 8; nt++)
#pragma unroll
            for (int e = 0; e < 4; e++) c[nt][e] = 0.f;
        float la = 0.f, lb = 0.f;
        for (int jg = 0; jg < 49; jg++) {
            int jbase = jg * 16;
            float4 kk0 = *(const float4*)&kxy[jbase + 2 * tig];
            float4 kk1 = *(const float4*)&kxy[jbase + 2 * tig + 8];
            float p00 = exp2f(fmaf(q0.x, kk0.x, q0.y * kk0.y));
            float p01 = exp2f(fmaf(q0.x, kk0.z, q0.y * kk0.w));
            float p02 = exp2f(fmaf(q0.x, kk1.x, q0.y * kk1.y));
            float p03 = exp2f(fmaf(q0.x, kk1.z, q0.y * kk1.w));
            float p10 = exp2f(fmaf(q1.x, kk0.x, q1.y * kk0.y));
            float p11 = exp2f(fmaf(q1.x, kk0.z, q1.y * kk0.w));
            float p12 = exp2f(fmaf(q1.x, kk1.x, q1.y * kk1.y));
            float p13 = exp2f(fmaf(q1.x, kk1.z, q1.y * kk1.w));
            la += (p00 + p01) + (p02 + p03);
            lb += (p10 + p11) + (p12 + p13);
            uint32_t a0 = pack_h2(p00, p01), a1 = pack_h2(p10, p11);
            uint32_t a2 = pack_h2(p02, p03), a3 = pack_h2(p12, p13);
            const uint2* vrow = &Vp[(jg * 64) * 4 + tig];
#pragma unroll
            for (int nt = 0; nt < 8; nt++) {
                uint2 bb = vrow[(nt * 8 + g) * 4];
                mma_h(c[nt], a0, a1, a2, a3, bb.x, bb.y);
            }
        }
        la += __shfl_xor_sync(0xffffffffu, la, 1);
        la += __shfl_xor_sync(0xffffffffu, la, 2);
        lb += __shfl_xor_sync(0xffffffffu, lb, 1);
        lb += __shfl_xor_sync(0xffffffffu, lb, 2);
        float i0 = 1.f / la, i1 = 1.f / lb;
#pragma unroll
        for (int nt = 0; nt < 8; nt++) {
            int n = nt * 8 + 2 * tig;
            *(uint32_t*)&odst[(size_t)r0 * INNER + n] = pack_h2(c[nt][0] * i0, c[nt][1] * i0);
            *(uint32_t*)&odst[(size_t)r1 * INNER + n] = pack_h2(c[nt][2] * i1, c[nt][3] * i1);
        }
    }
}

// ---------------- 7) bicubic x2 upsample, paired output rows ---------------
// block = (m, b): produces rows oy=2m (W75, taps m-2..m+1) and oy=2m+1 (W25, taps m-1..m+2)
// dynamic smem: 2*28*256 floats = 57344 B (over the 48KB static limit)
__global__ void upsample3_kernel(float* __restrict__ out) {
    extern __shared__ float tmp[];   // [2][PP][DIM]
    float* tmp0 = tmp;
    float* tmp1 = tmp + PP * DIM;
    int m = blockIdx.x, b = blockIdx.y, c = threadIdx.x;
    int ry[5];
#pragma unroll
    for (int r = 0; r < 5; r++) ry[r] = min(max(m - 2 + r, 0), PP - 1);
    const float* basep = g_y28 + (size_t)b * NPOS * DIM + c;
#pragma unroll 7
    for (int ix = 0; ix < PP; ix++) {
        float v0 = basep[(size_t)(ry[0] * PP + ix) * DIM];
        float v1 = basep[(size_t)(ry[1] * PP + ix) * DIM];
        float v2 = basep[(size_t)(ry[2] * PP + ix) * DIM];
        float v3 = basep[(size_t)(ry[3] * PP + ix) * DIM];
        float v4 = basep[(size_t)(ry[4] * PP + ix) * DIM];
        tmp0[ix * DIM + c] = c_W75[0] * v0 + c_W75[1] * v1 + c_W75[2] * v2 + c_W75[3] * v3;
        tmp1[ix * DIM + c] = c_W25[0] * v1 + c_W25[1] * v2 + c_W25[2] * v3 + c_W25[3] * v4;
    }
    __syncthreads();
    float* orow0 = out + ((size_t)b * IMG * IMG + (2 * m) * IMG) * DIM + c;
    float* orow1 = orow0 + (size_t)IMG * DIM;
#pragma unroll 4
    for (int ox = 0; ox < IMG; ox++) {
        int ix0; const float* wx;
        if (ox & 1) { ix0 = (ox - 1) >> 1; wx = c_W25; }
        else        { ix0 = (ox >> 1) - 1; wx = c_W75; }
        int sx0 = min(max(ix0 - 1, 0), PP - 1);
        int sx1 = min(max(ix0 + 0, 0), PP - 1);
        int sx2 = min(max(ix0 + 1, 0), PP - 1);
        int sx3 = min(max(ix0 + 2, 0), PP - 1);
        float a0 = wx[0] * tmp0[sx0 * DIM + c] + wx[1] * tmp0[sx1 * DIM + c]
                 + wx[2] * tmp0[sx2 * DIM + c] + wx[3] * tmp0[sx3 * DIM + c];
        float a1 = wx[0] * tmp1[sx0 * DIM + c] + wx[1] * tmp1[sx1 * DIM + c]
                 + wx[2] * tmp1[sx2 * DIM + c] + wx[3] * tmp1[sx3 * DIM + c];
        orow0[(size_t)ox * DIM] = a0;
        orow1[(size_t)ox * DIM] = a1;
    }
}

// ---------------- launch ---------------------------------------------------
extern "C" void kernel_launch(void* const* d_in, const int* in_sizes, int n_in,
                              void* d_out, int out_size) {
    const float* x     = (const float*)d_in[0];
    const float* q_w   = (const float*)d_in[1];
    const float* q_b   = (const float*)d_in[2];
    const float* k_w   = (const float*)d_in[3];
    const float* k_b   = (const float*)d_in[4];
    const float* dw_w  = (const float*)d_in[5];
    const float* dw_b  = (const float*)d_in[6];
    const float* bn_g  = (const float*)d_in[7];
    const float* bn_b  = (const float*)d_in[8];
    const float* bn_m  = (const float*)d_in[9];
    const float* bn_v  = (const float*)d_in[10];
    const float* pw_w  = (const float*)d_in[11];
    const float* pw_b  = (const float*)d_in[12];
    const float* out_w = (const float*)d_in[13];
    const float* out_b = (const float*)d_in[14];
    float* out = (float*)d_out;

    const int ATTN_SMEM = 49 * 64 * 4 * 8 + NPOS * 8;          // 106624
    const int UPS_SMEM  = 2 * PP * DIM * (int)sizeof(float);   // 57344
    cudaFuncSetAttribute(attn_h_kernel, cudaFuncAttributeMaxDynamicSharedMemorySize, ATTN_SMEM);
    cudaFuncSetAttribute(upsample3_kernel, cudaFuncAttributeMaxDynamicSharedMemorySize, UPS_SMEM);

    void *p_vmid, *p_v, *p_ao, *p_y28, *p_pww, *p_oww;
    cudaGetSymbolAddress(&p_vmid, g_vmid_h);
    cudaGetSymbolAddress(&p_v, g_v_h);
    cudaGetSymbolAddress(&p_ao, g_ao_h);
    cudaGetSymbolAddress(&p_y28, g_y28);
    cudaGetSymbolAddress(&p_pww, g_pww_h);
    cudaGetSymbolAddress(&p_oww, g_oww_h);

    round_weights_kernel<<<(INNER * DIM + 255) / 256, 256>>>(pw_w, out_w);
    pool_part_kernel<<<dim3(4, PP, BATCH), 256>>>(x);
    qk_conv_kernel<<<dim3(NPOS / 8, BATCH), 256>>>(q_w, q_b, k_w, k_b);
    dw_part_kernel<<<dim3(4, PP, BATCH), 256>>>(dw_w, dw_b, bn_g, bn_b, bn_m, bn_v);
    // pointwise conv: [12544,256] x [512,256]^T -> fp16 [12544,512]
    gemm_h_kernel<<<dim3(INNER / 64, (BATCH * NPOS) / 128), 256>>>(
        (const __half*)p_vmid, (const __half*)p_pww, pw_b, p_v,
        BATCH * NPOS, INNER, DIM, 1);
    attn_h_kernel<<<dim3(HEADS, BATCH), 800, ATTN_SMEM>>>();
    // output projection: [12544,512] x [256,512]^T -> fp32 [12544,256]
    gemm_h_kernel<<<dim3(DIM / 64, (BATCH * NPOS) / 128), 256>>>(
        (const __half*)p_ao, (const __half*)p_oww, out_b, p_y28,
        BATCH * NPOS, DIM, INNER, 0);
    upsample3_kernel<<<dim3(PP, BATCH), 256, UPS_SMEM>>>(out);
}

// round 9
// speedup vs baseline: 4.5341x; 1.0234x over previous
#include <cuda_runtime.h>
#include <cuda_fp16.h>
#include <math.h>
#include <stdint.h>

#define BATCH 16
#define IMG 56
#define PP 28
#define NPOS 784
#define DIM 256
#define HEADS 8
#define DH 64
#define INNER 512
#define ATHREADS 416   // 13 warps

// ---------------- scratch (static device allocations; no cudaMalloc) -------
__device__ float  g_xpool[BATCH * NPOS * DIM];    // pooled fp32 [b, p, c]
__device__ float  g_attn2[BATCH * NPOS * 2];      // mean/max over channels
__device__ float  g_q[BATCH * HEADS * NPOS * 2];
__device__ float  g_k[BATCH * HEADS * NPOS * 2];
__device__ __half g_vmid_h[BATCH * NPOS * DIM];   // after dw+BN+GELU (fp16)
__device__ __half g_v_h[BATCH * NPOS * INNER];    // after pointwise conv (fp16)
__device__ __half g_ao_h[BATCH * NPOS * INNER];   // attention out (fp16)
__device__ float  g_y28[BATCH * NPOS * DIM];      // after out-proj (fp32)
__device__ __half g_pww_h[INNER * DIM];           // fp16 pw_w
__device__ __half g_oww_h[DIM * INNER];           // fp16 out_w

// bicubic (a=-0.75) weights for t=0.25 and t=0.75 (half-pixel, x2)
__constant__ float c_W25[4] = {-0.10546875f, 0.87890625f, 0.26171875f, -0.03515625f};
__constant__ float c_W75[4] = {-0.03515625f, 0.26171875f, 0.87890625f, -0.10546875f};

// ---------------- fp16 helpers ---------------------------------------------
__device__ __forceinline__ uint32_t pack_h2(float lo, float hi) {
    uint32_t r;
    asm("cvt.rn.f16x2.f32 %0, %1, %2;" : "=r"(r) : "f"(hi), "f"(lo));
    return r;
}

// 2^x on both fp16 halves via one MUFU op; result IS an mma A-fragment word.
__device__ __forceinline__ uint32_t exp2_h2(float lo, float hi) {
    uint32_t s = pack_h2(lo, hi);
    uint32_t r;
    asm("ex2.approx.f16x2 %0, %1;" : "=r"(r) : "r"(s));
    return r;
}

__device__ __forceinline__ void mma_h(float c[4], uint32_t a0, uint32_t a1,
                                      uint32_t a2, uint32_t a3,
                                      uint32_t b0, uint32_t b1) {
    asm volatile(
        "mma.sync.aligned.m16n8k16.row.col.f32.f16.f16.f32 "
        "{%0,%1,%2,%3},{%4,%5,%6,%7},{%8,%9},{%0,%1,%2,%3};"
        : "+f"(c[0]), "+f"(c[1]), "+f"(c[2]), "+f"(c[3])
        : "r"(a0), "r"(a1), "r"(a2), "r"(a3), "r"(b0), "r"(b1));
}

// ---------------- 0) convert weights to fp16 once --------------------------
__global__ void round_weights_kernel(const float* __restrict__ pw,
                                     const float* __restrict__ ow) {
    int i = blockIdx.x * 256 + threadIdx.x;
    if (i < INNER * DIM) {
        g_pww_h[i] = __float2half(pw[i]);
        g_oww_h[i] = __float2half(ow[i]);
    }
}

// ---------------- 1) avgpool(3,2,1) + channel mean/max (px-split) ----------
__global__ void pool_part_kernel(const float* __restrict__ x) {
    __shared__ float srow[7][DIM];
    int quarter = blockIdx.x, py = blockIdx.y, b = blockIdx.z;
    int c = threadIdx.x, lane = c & 31, w = c >> 5;
    int px0 = quarter * 7;
    const float* base = x + (size_t)b * IMG * IMG * DIM + c;
    int rm = 2 * py - 1, r0 = 2 * py, rp = 2 * py + 1;
    bool vm = rm >= 0;

    float cs[15];
#pragma unroll
    for (int i = 0; i < 15; i++) {
        int ix = 2 * px0 - 1 + i;
        if ((unsigned)ix < IMG) {
            float v = base[(size_t)(r0 * IMG + ix) * DIM] + base[(size_t)(rp * IMG + ix) * DIM];
            if (vm) v += base[(size_t)(rm * IMG + ix) * DIM];
            cs[i] = v;
        } else cs[i] = 0.f;
    }
    float* outp = g_xpool + ((size_t)b * NPOS + py * PP + px0) * DIM + c;
#pragma unroll
    for (int i = 0; i < 7; i++) {
        float pool = (cs[2 * i] + cs[2 * i + 1] + cs[2 * i + 2]) * (1.f / 9.f);
        outp[(size_t)i * DIM] = pool;
        srow[i][c] = pool;
    }
    __syncthreads();
    if (w < 7) {
        float s = 0.f, m = -1e30f;
#pragma unroll
        for (int k = 0; k < 8; k++) {
            float v = srow[w][lane + 32 * k];
            s += v; m = fmaxf(m, v);
        }
#pragma unroll
        for (int o = 16; o > 0; o >>= 1) {
            s += __shfl_down_sync(0xffffffffu, s, o);
            m = fmaxf(m, __shfl_down_sync(0xffffffffu, m, o));
        }
        if (lane == 0) {
            g_attn2[((size_t)b * NPOS + py * PP + px0 + w) * 2 + 0] = s * (1.f / DIM);
            g_attn2[((size_t)b * NPOS + py * PP + px0 + w) * 2 + 1] = m;
        }
    }
}

// ---------------- 2) q/k 3x3 convs (8 positions per block) -----------------
__global__ void qk_conv_kernel(const float* __restrict__ qw, const float* __restrict__ qb,
                               const float* __restrict__ kw, const float* __restrict__ kb) {
    int t = threadIdx.x;
    int p = blockIdx.x * 8 + (t >> 5), b = blockIdx.y;
    int tt = t & 31;
    int sel = tt >> 4, och = tt & 15;
    const float* w = sel ? kw : qw;
    const float* bi = sel ? kb : qb;
    float* outp = sel ? g_k : g_q;
    int py = p / PP, px = p % PP;
    float acc = bi[och];
#pragma unroll
    for (int dy = 0; dy < 3; dy++) {
        int iy = py - 1 + dy;
        if ((unsigned)iy >= PP) continue;
#pragma unroll
        for (int dx = 0; dx < 3; dx++) {
            int ix = px - 1 + dx;
            if ((unsigned)ix >= PP) continue;
            const float* a2 = &g_attn2[((size_t)b * NPOS + iy * PP + ix) * 2];
            acc += w[((och * 2 + 0) * 3 + dy) * 3 + dx] * a2[0]
                 + w[((och * 2 + 1) * 3 + dy) * 3 + dx] * a2[1];
        }
    }
    int h = och >> 1, comp = och & 1;
    outp[(((size_t)b * HEADS + h) * NPOS + p) * 2 + comp] = acc;
}

// ---------------- 3) depthwise 3x3 + BN + GELU (px-split, fp16 out) --------
__global__ void dw_part_kernel(const float* __restrict__ dww, const float* __restrict__ dwb,
                               const float* __restrict__ gamma, const float* __restrict__ beta,
                               const float* __restrict__ mean, const float* __restrict__ var) {
    int quarter = blockIdx.x, py = blockIdx.y, b = blockIdx.z, c = threadIdx.x;
    int px0 = quarter * 7;
    float wgt[9];
#pragma unroll
    for (int k = 0; k < 9; k++) wgt[k] = dww[c * 9 + k];
    float bias = dwb[c];
    float sc = gamma[c] * rsqrtf(var[c] + 1e-5f);
    float bm = mean[c], bb = beta[c];

    const float* basep = g_xpool + (size_t)b * NPOS * DIM + c;
    float vin[3][9];
#pragma unroll
    for (int r = 0; r < 3; r++) {
        int row = py - 1 + r;
        bool vr = (unsigned)row < PP;
#pragma unroll
        for (int cc = 0; cc < 9; cc++) {
            int col = px0 - 1 + cc;
            vin[r][cc] = (vr && (unsigned)col < PP)
                       ? basep[(size_t)(row * PP + col) * DIM] : 0.f;
        }
    }
    __half* outp = g_vmid_h + ((size_t)b * NPOS + py * PP + px0) * DIM + c;
#pragma unroll
    for (int i = 0; i < 7; i++) {
        float acc = bias;
#pragma unroll
        for (int r = 0; r < 3; r++)
#pragma unroll
            for (int d = 0; d < 3; d++)
                acc = fmaf(wgt[r * 3 + d], vin[r][i + d], acc);
        acc = (acc - bm) * sc + bb;
        acc = 0.5f * acc * (1.f + erff(acc * 0.70710678118654752f));
        outp[(size_t)i * DIM] = __float2half(acc);
    }
}

// ---------------- fp16 mma GEMM: C[M,N] = A[M,K]*B[N,K]^T + bias -----------
// 128x128 block tile, 256 threads (8 warps 4x2; warp tile 32x64), K-chunk 32.
__global__ __launch_bounds__(256) void gemm_h_kernel(
        const __half* __restrict__ A, const __half* __restrict__ B,
        const float* __restrict__ bias, void* __restrict__ Cv,
        int M, int N, int K, int out_half) {
    __shared__ uint2 As2[2][2][128][4];
    __shared__ uint2 Bs2[2][2][128][4];
    int tid = threadIdx.x;
    int lane = tid & 31, w = tid >> 5, g = lane >> 2, tig = lane & 3;
    int wm = w >> 1, wn = w & 1;          // wm: 4x32 rows, wn: 2x64 cols
    int m0 = blockIdx.y * 128, n0 = blockIdx.x * 128;
    float c[2][8][4] = {};

    int nchunks = K >> 5;
    int arow[2], aq[2];
#pragma unroll
    for (int i = 0; i < 2; i++) { int s = tid + i * 256; arow[i] = s >> 2; aq[i] = s & 3; }
    uint4 ra[2], rb[2];

#pragma unroll
    for (int i = 0; i < 2; i++) {
        ra[i] = *(const uint4*)&A[(size_t)(m0 + arow[i]) * K + aq[i] * 8];
        rb[i] = *(const uint4*)&B[(size_t)(n0 + arow[i]) * K + aq[i] * 8];
    }

#pragma unroll
    for (int i = 0; i < 2; i++) {
        uint32_t* pa = (uint32_t*)&As2[0][aq[i] >> 1][arow[i]][0] + (aq[i] & 1);
        pa[0] = ra[i].x; pa[2] = ra[i].y; pa[4] = ra[i].z; pa[6] = ra[i].w;
        uint32_t* pb = (uint32_t*)&Bs2[0][aq[i] >> 1][arow[i]][0] + (aq[i] & 1);
        pb[0] = rb[i].x; pb[2] = rb[i].y; pb[4] = rb[i].z; pb[6] = rb[i].w;
    }
    __syncthreads();

    for (int kc = 0; kc < nchunks; kc++) {
        int cur = kc & 1;
        if (kc + 1 < nchunks) {
            int ko = (kc + 1) * 32;
#pragma unroll
            for (int i = 0; i < 2; i++) {
                ra[i] = *(const uint4*)&A[(size_t)(m0 + arow[i]) * K + ko + aq[i] * 8];
                rb[i] = *(const uint4*)&B[(size_t)(n0 + arow[i]) * K + ko + aq[i] * 8];
            }
        }
#pragma unroll
        for (int kg = 0; kg < 2; kg++) {
            uint2 a00 = As2[cur][kg][wm * 32 + g][tig];
            uint2 a08 = As2[cur][kg][wm * 32 + 8 + g][tig];
            uint2 a16 = As2[cur][kg][wm * 32 + 16 + g][tig];
            uint2 a24 = As2[cur][kg][wm * 32 + 24 + g][tig];
#pragma unroll
            for (int nt = 0; nt < 8; nt++) {
                uint2 bb = Bs2[cur][kg][wn * 64 + nt * 8 + g][tig];
                mma_h(c[0][nt], a00.x, a08.x, a00.y, a08.y, bb.x, bb.y);
                mma_h(c[1][nt], a16.x, a24.x, a16.y, a24.y, bb.x, bb.y);
            }
        }
        if (kc + 1 < nchunks) {
            int nxt = cur ^ 1;
#pragma unroll
            for (int i = 0; i < 2; i++) {
                uint32_t* pa = (uint32_t*)&As2[nxt][aq[i] >> 1][arow[i]][0] + (aq[i] & 1);
                pa[0] = ra[i].x; pa[2] = ra[i].y; pa[4] = ra[i].z; pa[6] = ra[i].w;
                uint32_t* pb = (uint32_t*)&Bs2[nxt][aq[i] >> 1][arow[i]][0] + (aq[i] & 1);
                pb[0] = rb[i].x; pb[2] = rb[i].y; pb[4] = rb[i].z; pb[6] = rb[i].w;
            }
            __syncthreads();
        }
    }
#pragma unroll
    for (int mt = 0; mt < 2; mt++) {
        int r = m0 + wm * 32 + mt * 16 + g;
#pragma unroll
        for (int nt = 0; nt < 8; nt++) {
            int n = n0 + wn * 64 + nt * 8 + 2 * tig;
            float bx = bias[n], by = bias[n + 1];
            float o0 = c[mt][nt][0] + bx, o1 = c[mt][nt][1] + by;
            float o2 = c[mt][nt][2] + bx, o3 = c[mt][nt][3] + by;
            if (out_half) {
                __half* C = (__half*)Cv;
                *(uint32_t*)&C[(size_t)r * N + n] = pack_h2(o0, o1);
                *(uint32_t*)&C[(size_t)(r + 8) * N + n] = pack_h2(o2, o3);
            } else {
                float* C = (float*)Cv;
                *(float2*)&C[(size_t)r * N + n] = make_float2(o0, o1);
                *(float2*)&C[(size_t)(r + 8) * N + n] = make_float2(o2, o3);
            }
        }
    }
}

// ---------------- 5) attention per (b,h): fp16 mma, fp16x2 MUFU exp --------
// p = 2^(s*log2e) computed in fp16x2 directly into A-frags; row-sums l via an
// extra mma against an all-ones B; 2 query tiles per jg sweep (13 warps).
__global__ __launch_bounds__(ATHREADS, 1) void attn_h_kernel() {
    extern __shared__ char smc[];
    uint2* Vp = (uint2*)smc;                         // [49][64][4] : 100352 B
    float2* kxy = (float2*)(smc + 49 * 64 * 4 * 8);  // 784 float2 : 6272 B
    int h = blockIdx.x, b = blockIdx.y;
    int tid = threadIdx.x, lane = tid & 31, w = tid >> 5;
    int g = lane >> 2, tig = lane & 3;
    const uint32_t ONES = 0x3C003C00u;               // (1.0h, 1.0h)

    const __half* vsrc = g_v_h + (size_t)b * NPOS * INNER + h * DH;
    for (int i = tid; i < 392 * 32; i += ATHREADS) {
        int jp = i >> 5, n2 = (i & 31) * 2;
        uint32_t a = *(const uint32_t*)&vsrc[(size_t)(2 * jp) * INNER + n2];
        uint32_t bu = *(const uint32_t*)&vsrc[(size_t)(2 * jp + 1) * INNER + n2];
        uint32_t o0 = __byte_perm(a, bu, 0x5410);
        uint32_t o1 = __byte_perm(a, bu, 0x7632);
        int jg = jp >> 3, lp = jp & 7;
        int t4 = lp & 3, hf = lp >> 2;
        ((uint32_t*)&Vp[(jg * 64 + n2) * 4 + t4])[hf] = o0;
        ((uint32_t*)&Vp[(jg * 64 + n2 + 1) * 4 + t4])[hf] = o1;
    }
    const float* ksrc = g_k + ((size_t)b * HEADS + h) * NPOS * 2;
    const float KSC = 0.125f * 1.4426950408889634f;  // scale * log2(e)
    for (int i = tid; i < NPOS; i += ATHREADS) {
        float2 kv = ((const float2*)ksrc)[i];
        kxy[i] = make_float2(kv.x * KSC, kv.y * KSC);
    }
    __syncthreads();

    const float2* qsrc = (const float2*)(g_q + ((size_t)b * HEADS + h) * NPOS * 2);
    __half* odst = g_ao_h + (size_t)b * NPOS * INNER + h * DH;

    for (int s = w; s < 25; s += 13) {
        int t0 = 2 * s, t1 = 2 * s + 1;   // t1 == 49 is invalid (s == 24)
        bool v1 = t1 < 49;
        int r00 = t0 * 16 + g, r01 = r00 + 8;
        int r10 = t1 * 16 + g, r11 = r10 + 8;
        float2 qA0 = qsrc[r00], qA1 = qsrc[r01];
        float2 qB0 = v1 ? qsrc[r10] : make_float2(0.f, 0.f);
        float2 qB1 = v1 ? qsrc[r11] : make_float2(0.f, 0.f);
        float cA[8][4] = {}, cB[8][4] = {};
        float clA[4] = {}, clB[4] = {};
        for (int jg = 0; jg < 49; jg++) {
            float4 kk0 = *(const float4*)&kxy[jg * 16 + 2 * tig];
            float4 kk1 = *(const float4*)&kxy[jg * 16 + 2 * tig + 8];
            uint32_t a0 = exp2_h2(fmaf(qA0.x, kk0.x, qA0.y * kk0.y),
                                  fmaf(qA0.x, kk0.z, qA0.y * kk0.w));
            uint32_t a1 = exp2_h2(fmaf(qA1.x, kk0.x, qA1.y * kk0.y),
                                  fmaf(qA1.x, kk0.z, qA1.y * kk0.w));
            uint32_t a2 = exp2_h2(fmaf(qA0.x, kk1.x, qA0.y * kk1.y),
                                  fmaf(qA0.x, kk1.z, qA0.y * kk1.w));
            uint32_t a3 = exp2_h2(fmaf(qA1.x, kk1.x, qA1.y * kk1.y),
                                  fmaf(qA1.x, kk1.z, qA1.y * kk1.w));
            uint32_t a4 = exp2_h2(fmaf(qB0.x, kk0.x, qB0.y * kk0.y),
                                  fmaf(qB0.x, kk0.z, qB0.y * kk0.w));
            uint32_t a5 = exp2_h2(fmaf(qB1.x, kk0.x, qB1.y * kk0.y),
                                  fmaf(qB1.x, kk0.z, qB1.y * kk0.w));
            uint32_t a6 = exp2_h2(fmaf(qB0.x, kk1.x, qB0.y * kk1.y),
                                  fmaf(qB0.x, kk1.z, qB0.y * kk1.w));
            uint32_t a7 = exp2_h2(fmaf(qB1.x, kk1.x, qB1.y * kk1.y),
                                  fmaf(qB1.x, kk1.z, qB1.y * kk1.w));
            const uint2* vrow = &Vp[(jg * 64) * 4 + tig];
#pragma unroll
            for (int nt = 0; nt < 8; nt++) {
                uint2 bb = vrow[(nt * 8 + g) * 4];
                mma_h(cA[nt], a0, a1, a2, a3, bb.x, bb.y);
                mma_h(cB[nt], a4, a5, a6, a7, bb.x, bb.y);
            }
            mma_h(clA, a0, a1, a2, a3, ONES, ONES);
            mma_h(clB, a4, a5, a6, a7, ONES, ONES);
        }
        float i00 = 1.f / clA[0], i01 = 1.f / clA[2];
#pragma unroll
        for (int nt = 0; nt < 8; nt++) {
            int n = nt * 8 + 2 * tig;
            *(uint32_t*)&odst[(size_t)r00 * INNER + n] = pack_h2(cA[nt][0] * i00, cA[nt][1] * i00);
            *(uint32_t*)&odst[(size_t)r01 * INNER + n] = pack_h2(cA[nt][2] * i01, cA[nt][3] * i01);
        }
        if (v1) {
            float i10 = 1.f / clB[0], i11 = 1.f / clB[2];
#pragma unroll
            for (int nt = 0; nt < 8; nt++) {
                int n = nt * 8 + 2 * tig;
                *(uint32_t*)&odst[(size_t)r10 * INNER + n] = pack_h2(cB[nt][0] * i10, cB[nt][1] * i10);
                *(uint32_t*)&odst[(size_t)r11 * INNER + n] = pack_h2(cB[nt][2] * i11, cB[nt][3] * i11);
            }
        }
    }
}

// ---------------- 7) bicubic x2 upsample, paired output rows ---------------
__global__ void upsample3_kernel(float* __restrict__ out) {
    extern __shared__ float tmp[];   // [2][PP][DIM]
    float* tmp0 = tmp;
    float* tmp1 = tmp + PP * DIM;
    int m = blockIdx.x, b = blockIdx.y, c = threadIdx.x;
    int ry[5];
#pragma unroll
    for (int r = 0; r < 5; r++) ry[r] = min(max(m - 2 + r, 0), PP - 1);
    const float* basep = g_y28 + (size_t)b * NPOS * DIM + c;
#pragma unroll 7
    for (int ix = 0; ix < PP; ix++) {
        float v0 = basep[(size_t)(ry[0] * PP + ix) * DIM];
        float v1 = basep[(size_t)(ry[1] * PP + ix) * DIM];
        float v2 = basep[(size_t)(ry[2] * PP + ix) * DIM];
        float v3 = basep[(size_t)(ry[3] * PP + ix) * DIM];
        float v4 = basep[(size_t)(ry[4] * PP + ix) * DIM];
        tmp0[ix * DIM + c] = c_W75[0] * v0 + c_W75[1] * v1 + c_W75[2] * v2 + c_W75[3] * v3;
        tmp1[ix * DIM + c] = c_W25[0] * v1 + c_W25[1] * v2 + c_W25[2] * v3 + c_W25[3] * v4;
    }
    __syncthreads();
    float* orow0 = out + ((size_t)b * IMG * IMG + (2 * m) * IMG) * DIM + c;
    float* orow1 = orow0 + (size_t)IMG * DIM;
#pragma unroll 4
    for (int ox = 0; ox < IMG; ox++) {
        int ix0; const float* wx;
        if (ox & 1) { ix0 = (ox - 1) >> 1; wx = c_W25; }
        else        { ix0 = (ox >> 1) - 1; wx = c_W75; }
        int sx0 = min(max(ix0 - 1, 0), PP - 1);
        int sx1 = min(max(ix0 + 0, 0), PP - 1);
        int sx2 = min(max(ix0 + 1, 0), PP - 1);
        int sx3 = min(max(ix0 + 2, 0), PP - 1);
        float a0 = wx[0] * tmp0[sx0 * DIM + c] + wx[1] * tmp0[sx1 * DIM + c]
                 + wx[2] * tmp0[sx2 * DIM + c] + wx[3] * tmp0[sx3 * DIM + c];
        float a1 = wx[0] * tmp1[sx0 * DIM + c] + wx[1] * tmp1[sx1 * DIM + c]
                 + wx[2] * tmp1[sx2 * DIM + c] + wx[3] * tmp1[sx3 * DIM + c];
        orow0[(size_t)ox * DIM] = a0;
        orow1[(size_t)ox * DIM] = a1;
    }
}

// ---------------- launch ---------------------------------------------------
extern "C" void kernel_launch(void* const* d_in, const int* in_sizes, int n_in,
                              void* d_out, int out_size) {
    const float* x     = (const float*)d_in[0];
    const float* q_w   = (const float*)d_in[1];
    const float* q_b   = (const float*)d_in[2];
    const float* k_w   = (const float*)d_in[3];
    const float* k_b   = (const float*)d_in[4];
    const float* dw_w  = (const float*)d_in[5];
    const float* dw_b  = (const float*)d_in[6];
    const float* bn_g  = (const float*)d_in[7];
    const float* bn_b  = (const float*)d_in[8];
    const float* bn_m  = (const float*)d_in[9];
    const float* bn_v  = (const float*)d_in[10];
    const float* pw_w  = (const float*)d_in[11];
    const float* pw_b  = (const float*)d_in[12];
    const float* out_w = (const float*)d_in[13];
    const float* out_b = (const float*)d_in[14];
    float* out = (float*)d_out;

    // pad > 114KB so only one attention block fits per SM (128 blocks ~ 1 wave)
    const int ATTN_SMEM = 120832;
    const int UPS_SMEM  = 2 * PP * DIM * (int)sizeof(float);   // 57344
    cudaFuncSetAttribute(attn_h_kernel, cudaFuncAttributeMaxDynamicSharedMemorySize, ATTN_SMEM);
    cudaFuncSetAttribute(upsample3_kernel, cudaFuncAttributeMaxDynamicSharedMemorySize, UPS_SMEM);

    void *p_vmid, *p_v, *p_ao, *p_y28, *p_pww, *p_oww;
    cudaGetSymbolAddress(&p_vmid, g_vmid_h);
    cudaGetSymbolAddress(&p_v, g_v_h);
    cudaGetSymbolAddress(&p_ao, g_ao_h);
    cudaGetSymbolAddress(&p_y28, g_y28);
    cudaGetSymbolAddress(&p_pww, g_pww_h);
    cudaGetSymbolAddress(&p_oww, g_oww_h);

    round_weights_kernel<<<(INNER * DIM + 255) / 256, 256>>>(pw_w, out_w);
    pool_part_kernel<<<dim3(4, PP, BATCH), 256>>>(x);
    qk_conv_kernel<<<dim3(NPOS / 8, BATCH), 256>>>(q_w, q_b, k_w, k_b);
    dw_part_kernel<<<dim3(4, PP, BATCH), 256>>>(dw_w, dw_b, bn_g, bn_b, bn_m, bn_v);
    // pointwise conv: [12544,256] x [512,256]^T -> fp16 [12544,512]
    gemm_h_kernel<<<dim3(INNER / 128, (BATCH * NPOS) / 128), 256>>>(
        (const __half*)p_vmid, (const __half*)p_pww, pw_b, p_v,
        BATCH * NPOS, INNER, DIM, 1);
    attn_h_kernel<<<dim3(HEADS, BATCH), ATHREADS, ATTN_SMEM>>>();
    // output projection: [12544,512] x [256,512]^T -> fp32 [12544,256]
    gemm_h_kernel<<<dim3(DIM / 128, (BATCH * NPOS) / 128), 256>>>(
        (const __half*)p_ao, (const __half*)p_oww, out_b, p_y28,
        BATCH * NPOS, DIM, INNER, 0);
    upsample3_kernel<<<dim3(PP, BATCH), 256, UPS_SMEM>>>(out);
}

// round 11
// speedup vs baseline: 4.5882x; 1.0119x over previous
#include <cuda_runtime.h>
#include <cuda_fp16.h>
#include <math.h>
#include <stdint.h>

#define BATCH 16
#define IMG 56
#define PP 28
#define NPOS 784
#define DIM 256
#define HEADS 8
#define DH 64
#define INNER 512

// ---------------- scratch (static device allocations; no cudaMalloc) -------
__device__ float  g_xpool[BATCH * NPOS * DIM];
__device__ float  g_attn2[BATCH * NPOS * 2];
__device__ float  g_q[BATCH * HEADS * NPOS * 2];
__device__ float  g_k[BATCH * HEADS * NPOS * 2];
__device__ __half g_vmid_h[BATCH * NPOS * DIM];
__device__ __half g_v_h[BATCH * NPOS * INNER];
__device__ __half g_ao_h[BATCH * NPOS * INNER];
__device__ float  g_y28[BATCH * NPOS * DIM];
__device__ __half g_pww_h[INNER * DIM];
__device__ __half g_oww_h[DIM * INNER];

__constant__ float c_W25[4] = {-0.10546875f, 0.87890625f, 0.26171875f, -0.03515625f};
__constant__ float c_W75[4] = {-0.03515625f, 0.26171875f, 0.87890625f, -0.10546875f};

// ---------------- fp16 helpers ---------------------------------------------
__device__ __forceinline__ uint32_t pack_h2(float lo, float hi) {
    uint32_t r;
    asm("cvt.rn.f16x2.f32 %0, %1, %2;" : "=r"(r) : "f"(hi), "f"(lo));
    return r;
}
// 2^x on both fp16 halves via one MUFU op; result IS an mma A-fragment word.
__device__ __forceinline__ uint32_t exp2_h2(float lo, float hi) {
    uint32_t s = pack_h2(lo, hi);
    uint32_t r;
    asm("ex2.approx.f16x2 %0, %1;" : "=r"(r) : "r"(s));
    return r;
}
__device__ __forceinline__ void mma_h(float c[4], uint32_t a0, uint32_t a1,
                                      uint32_t a2, uint32_t a3,
                                      uint32_t b0, uint32_t b1) {
    asm volatile(
        "mma.sync.aligned.m16n8k16.row.col.f32.f16.f16.f32 "
        "{%0,%1,%2,%3},{%4,%5,%6,%7},{%8,%9},{%0,%1,%2,%3};"
        : "+f"(c[0]), "+f"(c[1]), "+f"(c[2]), "+f"(c[3])
        : "r"(a0), "r"(a1), "r"(a2), "r"(a3), "r"(b0), "r"(b1));
}

// ---------------- 0) convert weights to fp16 once --------------------------
__global__ void round_weights_kernel(const float* __restrict__ pw,
                                     const float* __restrict__ ow) {
    int i = blockIdx.x * 256 + threadIdx.x;
    if (i < INNER * DIM) {
        g_pww_h[i] = __float2half(pw[i]);
        g_oww_h[i] = __float2half(ow[i]);
    }
}

// ---------------- 1) avgpool(3,2,1) + channel mean/max (px-split) ----------
__global__ void pool_part_kernel(const float* __restrict__ x) {
    __shared__ float srow[7][DIM];
    int quarter = blockIdx.x, py = blockIdx.y, b = blockIdx.z;
    int c = threadIdx.x, lane = c & 31, w = c >> 5;
    int px0 = quarter * 7;
    const float* base = x + (size_t)b * IMG * IMG * DIM + c;
    int rm = 2 * py - 1, r0 = 2 * py, rp = 2 * py + 1;
    bool vm = rm >= 0;

    float cs[15];
#pragma unroll
    for (int i = 0; i < 15; i++) {
        int ix = 2 * px0 - 1 + i;
        if ((unsigned)ix < IMG) {
            float v = base[(size_t)(r0 * IMG + ix) * DIM] + base[(size_t)(rp * IMG + ix) * DIM];
            if (vm) v += base[(size_t)(rm * IMG + ix) * DIM];
            cs[i] = v;
        } else cs[i] = 0.f;
    }
    float* outp = g_xpool + ((size_t)b * NPOS + py * PP + px0) * DIM + c;
#pragma unroll
    for (int i = 0; i < 7; i++) {
        float pool = (cs[2 * i] + cs[2 * i + 1] + cs[2 * i + 2]) * (1.f / 9.f);
        outp[(size_t)i * DIM] = pool;
        srow[i][c] = pool;
    }
    __syncthreads();
    if (w < 7) {
        float s = 0.f, m = -1e30f;
#pragma unroll
        for (int k = 0; k < 8; k++) {
            float v = srow[w][lane + 32 * k];
            s += v; m = fmaxf(m, v);
        }
#pragma unroll
        for (int o = 16; o > 0; o >>= 1) {
            s += __shfl_down_sync(0xffffffffu, s, o);
            m = fmaxf(m, __shfl_down_sync(0xffffffffu, m, o));
        }
        if (lane == 0) {
            g_attn2[((size_t)b * NPOS + py * PP + px0 + w) * 2 + 0] = s * (1.f / DIM);
            g_attn2[((size_t)b * NPOS + py * PP + px0 + w) * 2 + 1] = m;
        }
    }
}

// ---------------- 2) q/k 3x3 convs (8 positions per block) -----------------
__global__ void qk_conv_kernel(const float* __restrict__ qw, const float* __restrict__ qb,
                               const float* __restrict__ kw, const float* __restrict__ kb) {
    int t = threadIdx.x;
    int p = blockIdx.x * 8 + (t >> 5), b = blockIdx.y;
    int tt = t & 31;
    int sel = tt >> 4, och = tt & 15;
    const float* w = sel ? kw : qw;
    const float* bi = sel ? kb : qb;
    float* outp = sel ? g_k : g_q;
    int py = p / PP, px = p % PP;
    float acc = bi[och];
#pragma unroll
    for (int dy = 0; dy < 3; dy++) {
        int iy = py - 1 + dy;
        if ((unsigned)iy >= PP) continue;
#pragma unroll
        for (int dx = 0; dx < 3; dx++) {
            int ix = px - 1 + dx;
            if ((unsigned)ix >= PP) continue;
            const float* a2 = &g_attn2[((size_t)b * NPOS + iy * PP + ix) * 2];
            acc += w[((och * 2 + 0) * 3 + dy) * 3 + dx] * a2[0]
                 + w[((och * 2 + 1) * 3 + dy) * 3 + dx] * a2[1];
        }
    }
    int h = och >> 1, comp = och & 1;
    outp[(((size_t)b * HEADS + h) * NPOS + p) * 2 + comp] = acc;
}

// ---------------- 3) depthwise 3x3 + BN + GELU (px-split, fp16 out) --------
__global__ void dw_part_kernel(const float* __restrict__ dww, const float* __restrict__ dwb,
                               const float* __restrict__ gamma, const float* __restrict__ beta,
                               const float* __restrict__ mean, const float* __restrict__ var) {
    int quarter = blockIdx.x, py = blockIdx.y, b = blockIdx.z, c = threadIdx.x;
    int px0 = quarter * 7;
    float wgt[9];
#pragma unroll
    for (int k = 0; k < 9; k++) wgt[k] = dww[c * 9 + k];
    float bias = dwb[c];
    float sc = gamma[c] * rsqrtf(var[c] + 1e-5f);
    float bm = mean[c], bb = beta[c];

    const float* basep = g_xpool + (size_t)b * NPOS * DIM + c;
    float vin[3][9];
#pragma unroll
    for (int r = 0; r < 3; r++) {
        int row = py - 1 + r;
        bool vr = (unsigned)row < PP;
#pragma unroll
        for (int cc = 0; cc < 9; cc++) {
            int col = px0 - 1 + cc;
            vin[r][cc] = (vr && (unsigned)col < PP)
                       ? basep[(size_t)(row * PP + col) * DIM] : 0.f;
        }
    }
    __half* outp = g_vmid_h + ((size_t)b * NPOS + py * PP + px0) * DIM + c;
#pragma unroll
    for (int i = 0; i < 7; i++) {
        float acc = bias;
#pragma unroll
        for (int r = 0; r < 3; r++)
#pragma unroll
            for (int d = 0; d < 3; d++)
                acc = fmaf(wgt[r * 3 + d], vin[r][i + d], acc);
        acc = (acc - bm) * sc + bb;
        acc = 0.5f * acc * (1.f + erff(acc * 0.70710678118654752f));
        outp[(size_t)i * DIM] = __float2half(acc);
    }
}

// ---------------- fp16 mma GEMM: C[M,N] = A[M,K]*B[N,K]^T + bias -----------
// 128x128 block tile, 256 threads (8 warps 4x2; warp tile 32x64), K-chunk 32.
__global__ __launch_bounds__(256) void gemm_h_kernel(
        const __half* __restrict__ A, const __half* __restrict__ B,
        const float* __restrict__ bias, void* __restrict__ Cv,
        int M, int N, int K, int out_half) {
    __shared__ uint2 As2[2][2][128][4];
    __shared__ uint2 Bs2[2][2][128][4];
    int tid = threadIdx.x;
    int lane = tid & 31, w = tid >> 5, g = lane >> 2, tig = lane & 3;
    int wm = w >> 1, wn = w & 1;
    int m0 = blockIdx.y * 128, n0 = blockIdx.x * 128;
    float c[2][8][4] = {};

    int nchunks = K >> 5;
    int arow[2], aq[2];
#pragma unroll
    for (int i = 0; i < 2; i++) { int s = tid + i * 256; arow[i] = s >> 2; aq[i] = s & 3; }
    uint4 ra[2], rb[2];

#pragma unroll
    for (int i = 0; i < 2; i++) {
        ra[i] = *(const uint4*)&A[(size_t)(m0 + arow[i]) * K + aq[i] * 8];
        rb[i] = *(const uint4*)&B[(size_t)(n0 + arow[i]) * K + aq[i] * 8];
    }

#pragma unroll
    for (int i = 0; i < 2; i++) {
        uint32_t* pa = (uint32_t*)&As2[0][aq[i] >> 1][arow[i]][0] + (aq[i] & 1);
        pa[0] = ra[i].x; pa[2] = ra[i].y; pa[4] = ra[i].z; pa[6] = ra[i].w;
        uint32_t* pb = (uint32_t*)&Bs2[0][aq[i] >> 1][arow[i]][0] + (aq[i] & 1);
        pb[0] = rb[i].x; pb[2] = rb[i].y; pb[4] = rb[i].z; pb[6] = rb[i].w;
    }
    __syncthreads();

    for (int kc = 0; kc < nchunks; kc++) {
        int cur = kc & 1;
        if (kc + 1 < nchunks) {
            int ko = (kc + 1) * 32;
#pragma unroll
            for (int i = 0; i < 2; i++) {
                ra[i] = *(const uint4*)&A[(size_t)(m0 + arow[i]) * K + ko + aq[i] * 8];
                rb[i] = *(const uint4*)&B[(size_t)(n0 + arow[i]) * K + ko + aq[i] * 8];
            }
        }
#pragma unroll
        for (int kg = 0; kg < 2; kg++) {
            uint2 a00 = As2[cur][kg][wm * 32 + g][tig];
            uint2 a08 = As2[cur][kg][wm * 32 + 8 + g][tig];
            uint2 a16 = As2[cur][kg][wm * 32 + 16 + g][tig];
            uint2 a24 = As2[cur][kg][wm * 32 + 24 + g][tig];
#pragma unroll
            for (int nt = 0; nt < 8; nt++) {
                uint2 bb = Bs2[cur][kg][wn * 64 + nt * 8 + g][tig];
                mma_h(c[0][nt], a00.x, a08.x, a00.y, a08.y, bb.x, bb.y);
                mma_h(c[1][nt], a16.x, a24.x, a16.y, a24.y, bb.x, bb.y);
            }
        }
        if (kc + 1 < nchunks) {
            int nxt = cur ^ 1;
#pragma unroll
            for (int i = 0; i < 2; i++) {
                uint32_t* pa = (uint32_t*)&As2[nxt][aq[i] >> 1][arow[i]][0] + (aq[i] & 1);
                pa[0] = ra[i].x; pa[2] = ra[i].y; pa[4] = ra[i].z; pa[6] = ra[i].w;
                uint32_t* pb = (uint32_t*)&Bs2[nxt][aq[i] >> 1][arow[i]][0] + (aq[i] & 1);
                pb[0] = rb[i].x; pb[2] = rb[i].y; pb[4] = rb[i].z; pb[6] = rb[i].w;
            }
            __syncthreads();
        }
    }
#pragma unroll
    for (int mt = 0; mt < 2; mt++) {
        int r = m0 + wm * 32 + mt * 16 + g;
#pragma unroll
        for (int nt = 0; nt < 8; nt++) {
            int n = n0 + wn * 64 + nt * 8 + 2 * tig;
            float bx = bias[n], by = bias[n + 1];
            float o0 = c[mt][nt][0] + bx, o1 = c[mt][nt][1] + by;
            float o2 = c[mt][nt][2] + bx, o3 = c[mt][nt][3] + by;
            if (out_half) {
                __half* C = (__half*)Cv;
                *(uint32_t*)&C[(size_t)r * N + n] = pack_h2(o0, o1);
                *(uint32_t*)&C[(size_t)(r + 8) * N + n] = pack_h2(o2, o3);
            } else {
                float* C = (float*)Cv;
                *(float2*)&C[(size_t)r * N + n] = make_float2(o0, o1);
                *(float2*)&C[(size_t)(r + 8) * N + n] = make_float2(o2, o3);
            }
        }
    }
}

// ---------------- 5) attention per (b,h): legacy fp16 mma -------------------
// R8 structure (25 warps, 1 q-tile per sweep, ~70 regs) + fp16x2 MUFU exp
// (halves MUFU count) + row-sums via an extra mma against all-ones B.
__global__ __launch_bounds__(800, 1) void attn_h_kernel() {
    extern __shared__ char smc[];
    uint2* Vp = (uint2*)smc;                         // [49][64][4] : 100352 B
    float2* kxy = (float2*)(smc + 49 * 64 * 4 * 8);  // 784 float2 : 6272 B
    int h = blockIdx.x, b = blockIdx.y;
    int tid = threadIdx.x, lane = tid & 31, w = tid >> 5;
    int g = lane >> 2, tig = lane & 3;
    const uint32_t ONES = 0x3C003C00u;               // (1.0h, 1.0h)

    const __half* vsrc = g_v_h + (size_t)b * NPOS * INNER + h * DH;
    for (int i = tid; i < 392 * 32; i += 800) {
        int jp = i >> 5, n2 = (i & 31) * 2;
        uint32_t a = *(const uint32_t*)&vsrc[(size_t)(2 * jp) * INNER + n2];
        uint32_t bu = *(const uint32_t*)&vsrc[(size_t)(2 * jp + 1) * INNER + n2];
        uint32_t o0 = __byte_perm(a, bu, 0x5410);
        uint32_t o1 = __byte_perm(a, bu, 0x7632);
        int jg = jp >> 3, lp = jp & 7;
        int t4 = lp & 3, hf = lp >> 2;
        ((uint32_t*)&Vp[(jg * 64 + n2) * 4 + t4])[hf] = o0;
        ((uint32_t*)&Vp[(jg * 64 + n2 + 1) * 4 + t4])[hf] = o1;
    }
    const float* ksrc = g_k + ((size_t)b * HEADS + h) * NPOS * 2;
    const float KSC = 0.125f * 1.4426950408889634f;  // scale * log2(e)
    for (int i = tid; i < NPOS; i += 800) {
        float2 kv = ((const float2*)ksrc)[i];
        kxy[i] = make_float2(kv.x * KSC, kv.y * KSC);
    }
    __syncthreads();

    const float2* qsrc = (const float2*)(g_q + ((size_t)b * HEADS + h) * NPOS * 2);
    __half* odst = g_ao_h + (size_t)b * NPOS * INNER + h * DH;

    for (int t = w; t < 49; t += 25) {
        int r0 = t * 16 + g, r1 = r0 + 8;
        float2 q0 = qsrc[r0], q1 = qsrc[r1];
        float c[8][4] = {};
        float cl[4] = {};
        for (int jg = 0; jg < 49; jg++) {
            float4 kk0 = *(const float4*)&kxy[jg * 16 + 2 * tig];
            float4 kk1 = *(const float4*)&kxy[jg * 16 + 2 * tig + 8];
            uint32_t a0 = exp2_h2(fmaf(q0.x, kk0.x, q0.y * kk0.y),
                                  fmaf(q0.x, kk0.z, q0.y * kk0.w));
            uint32_t a1 = exp2_h2(fmaf(q1.x, kk0.x, q1.y * kk0.y),
                                  fmaf(q1.x, kk0.z, q1.y * kk0.w));
            uint32_t a2 = exp2_h2(fmaf(q0.x, kk1.x, q0.y * kk1.y),
                                  fmaf(q0.x, kk1.z, q0.y * kk1.w));
            uint32_t a3 = exp2_h2(fmaf(q1.x, kk1.x, q1.y * kk1.y),
                                  fmaf(q1.x, kk1.z, q1.y * kk1.w));
            const uint2* vrow = &Vp[(jg * 64) * 4 + tig];
#pragma unroll
            for (int nt = 0; nt < 8; nt++) {
                uint2 bb = vrow[(nt * 8 + g) * 4];
                mma_h(c[nt], a0, a1, a2, a3, bb.x, bb.y);
            }
            mma_h(cl, a0, a1, a2, a3, ONES, ONES);
        }
        float i0 = 1.f / cl[0], i1 = 1.f / cl[2];
#pragma unroll
        for (int nt = 0; nt < 8; nt++) {
            int n = nt * 8 + 2 * tig;
            *(uint32_t*)&odst[(size_t)r0 * INNER + n] = pack_h2(c[nt][0] * i0, c[nt][1] * i0);
            *(uint32_t*)&odst[(size_t)r1 * INNER + n] = pack_h2(c[nt][2] * i1, c[nt][3] * i1);
        }
    }
}

// ---------------- 7) bicubic x2 upsample, paired output rows ---------------
__global__ void upsample3_kernel(float* __restrict__ out) {
    extern __shared__ float tmp[];   // [2][PP][DIM] dynamic (57344 B)
    float* tmp0 = tmp;
    float* tmp1 = tmp + PP * DIM;
    int m = blockIdx.x, b = blockIdx.y, c = threadIdx.x;
    int ry[5];
#pragma unroll
    for (int r = 0; r < 5; r++) ry[r] = min(max(m - 2 + r, 0), PP - 1);
    const float* basep = g_y28 + (size_t)b * NPOS * DIM + c;
#pragma unroll 7
    for (int ix = 0; ix < PP; ix++) {
        float v0 = basep[(size_t)(ry[0] * PP + ix) * DIM];
        float v1 = basep[(size_t)(ry[1] * PP + ix) * DIM];
        float v2 = basep[(size_t)(ry[2] * PP + ix) * DIM];
        float v3 = basep[(size_t)(ry[3] * PP + ix) * DIM];
        float v4 = basep[(size_t)(ry[4] * PP + ix) * DIM];
        tmp0[ix * DIM + c] = c_W75[0] * v0 + c_W75[1] * v1 + c_W75[2] * v2 + c_W75[3] * v3;
        tmp1[ix * DIM + c] = c_W25[0] * v1 + c_W25[1] * v2 + c_W25[2] * v3 + c_W25[3] * v4;
    }
    __syncthreads();
    float* orow0 = out + ((size_t)b * IMG * IMG + (2 * m) * IMG) * DIM + c;
    float* orow1 = orow0 + (size_t)IMG * DIM;
#pragma unroll 4
    for (int ox = 0; ox < IMG; ox++) {
        int ix0; const float* wx;
        if (ox & 1) { ix0 = (ox - 1) >> 1; wx = c_W25; }
        else        { ix0 = (ox >> 1) - 1; wx = c_W75; }
        int sx0 = min(max(ix0 - 1, 0), PP - 1);
        int sx1 = min(max(ix0 + 0, 0), PP - 1);
        int sx2 = min(max(ix0 + 1, 0), PP - 1);
        int sx3 = min(max(ix0 + 2, 0), PP - 1);
        float a0 = wx[0] * tmp0[sx0 * DIM + c] + wx[1] * tmp0[sx1 * DIM + c]
                 + wx[2] * tmp0[sx2 * DIM + c] + wx[3] * tmp0[sx3 * DIM + c];
        float a1 = wx[0] * tmp1[sx0 * DIM + c] + wx[1] * tmp1[sx1 * DIM + c]
                 + wx[2] * tmp1[sx2 * DIM + c] + wx[3] * tmp1[sx3 * DIM + c];
        orow0[(size_t)ox * DIM] = a0;
        orow1[(size_t)ox * DIM] = a1;
    }
}

// ---------------- launch ---------------------------------------------------
extern "C" void kernel_launch(void* const* d_in, const int* in_sizes, int n_in,
                              void* d_out, int out_size) {
    const float* x     = (const float*)d_in[0];
    const float* q_w   = (const float*)d_in[1];
    const float* q_b   = (const float*)d_in[2];
    const float* k_w   = (const float*)d_in[3];
    const float* k_b   = (const float*)d_in[4];
    const float* dw_w  = (const float*)d_in[5];
    const float* dw_b  = (const float*)d_in[6];
    const float* bn_g  = (const float*)d_in[7];
    const float* bn_b  = (const float*)d_in[8];
    const float* bn_m  = (const float*)d_in[9];
    const float* bn_v  = (const float*)d_in[10];
    const float* pw_w  = (const float*)d_in[11];
    const float* pw_b  = (const float*)d_in[12];
    const float* out_w = (const float*)d_in[13];
    const float* out_b = (const float*)d_in[14];
    float* out = (float*)d_out;

    const int ATTN_SMEM = 49 * 64 * 4 * 8 + NPOS * 8;          // 106624
    const int UPS_SMEM  = 2 * PP * DIM * (int)sizeof(float);   // 57344
    cudaFuncSetAttribute(attn_h_kernel, cudaFuncAttributeMaxDynamicSharedMemorySize, ATTN_SMEM);
    cudaFuncSetAttribute(upsample3_kernel, cudaFuncAttributeMaxDynamicSharedMemorySize, UPS_SMEM);

    void *p_vmid, *p_v, *p_ao, *p_y28, *p_pww, *p_oww;
    cudaGetSymbolAddress(&p_vmid, g_vmid_h);
    cudaGetSymbolAddress(&p_v, g_v_h);
    cudaGetSymbolAddress(&p_ao, g_ao_h);
    cudaGetSymbolAddress(&p_y28, g_y28);
    cudaGetSymbolAddress(&p_pww, g_pww_h);
    cudaGetSymbolAddress(&p_oww, g_oww_h);

    round_weights_kernel<<<(INNER * DIM + 255) / 256, 256>>>(pw_w, out_w);
    pool_part_kernel<<<dim3(4, PP, BATCH), 256>>>(x);
    qk_conv_kernel<<<dim3(NPOS / 8, BATCH), 256>>>(q_w, q_b, k_w, k_b);
    dw_part_kernel<<<dim3(4, PP, BATCH), 256>>>(dw_w, dw_b, bn_g, bn_b, bn_m, bn_v);
    // pointwise conv: [12544,256] x [512,256]^T -> fp16 [12544,512]
    gemm_h_kernel<<<dim3(INNER / 128, (BATCH * NPOS) / 128), 256>>>(
        (const __half*)p_vmid, (const __half*)p_pww, pw_b, p_v,
        BATCH * NPOS, INNER, DIM, 1);
    attn_h_kernel<<<dim3(HEADS, BATCH), 800, ATTN_SMEM>>>();
    // output projection: [12544,512] x [256,512]^T -> fp32 [12544,256]
    gemm_h_kernel<<<dim3(DIM / 128, (BATCH * NPOS) / 128), 256>>>(
        (const __half*)p_ao, (const __half*)p_oww, out_b, p_y28,
        BATCH * NPOS, DIM, INNER, 0);
    upsample3_kernel<<<dim3(PP, BATCH), 256, UPS_SMEM>>>(out);
}

// round 12
// speedup vs baseline: 4.6429x; 1.0119x over previous
#include <cuda_runtime.h>
#include <cuda_fp16.h>
#include <math.h>
#include <stdint.h>

#define BATCH 16
#define IMG 56
#define PP 28
#define NPOS 784
#define DIM 256
#define HEADS 8
#define DH 64
#define INNER 512

// ---------------- scratch (static device allocations; no cudaMalloc) -------
__device__ float  g_xpool[BATCH * NPOS * DIM];
__device__ float  g_attn2[BATCH * NPOS * 2];
__device__ float  g_q[BATCH * HEADS * NPOS * 2];
__device__ float  g_k[BATCH * HEADS * NPOS * 2];
__device__ __half g_vmid_h[BATCH * NPOS * DIM];
__device__ __half g_v_h[BATCH * NPOS * INNER];
__device__ __half g_ao_h[BATCH * NPOS * INNER];
__device__ float  g_y28[BATCH * NPOS * DIM];
__device__ __half g_pww_h[INNER * DIM];
__device__ __half g_oww_h[DIM * INNER];

__constant__ float c_W25[4] = {-0.10546875f, 0.87890625f, 0.26171875f, -0.03515625f};
__constant__ float c_W75[4] = {-0.03515625f, 0.26171875f, 0.87890625f, -0.10546875f};

// ---------------- fp16 helpers ---------------------------------------------
__device__ __forceinline__ uint32_t pack_h2(float lo, float hi) {
    uint32_t r;
    asm("cvt.rn.f16x2.f32 %0, %1, %2;" : "=r"(r) : "f"(hi), "f"(lo));
    return r;
}
// 2^x on both fp16 halves via one MUFU op; result IS an mma A-fragment word.
__device__ __forceinline__ uint32_t exp2_h2(float lo, float hi) {
    uint32_t s = pack_h2(lo, hi);
    uint32_t r;
    asm("ex2.approx.f16x2 %0, %1;" : "=r"(r) : "r"(s));
    return r;
}
__device__ __forceinline__ void mma_h(float c[4], uint32_t a0, uint32_t a1,
                                      uint32_t a2, uint32_t a3,
                                      uint32_t b0, uint32_t b1) {
    asm volatile(
        "mma.sync.aligned.m16n8k16.row.col.f32.f16.f16.f32 "
        "{%0,%1,%2,%3},{%4,%5,%6,%7},{%8,%9},{%0,%1,%2,%3};"
        : "+f"(c[0]), "+f"(c[1]), "+f"(c[2]), "+f"(c[3])
        : "r"(a0), "r"(a1), "r"(a2), "r"(a3), "r"(b0), "r"(b1));
}

// ---------------- 0) convert weights to fp16 once --------------------------
__global__ void round_weights_kernel(const float* __restrict__ pw,
                                     const float* __restrict__ ow) {
    int i = blockIdx.x * 256 + threadIdx.x;
    if (i < INNER * DIM) {
        g_pww_h[i] = __float2half(pw[i]);
        g_oww_h[i] = __float2half(ow[i]);
    }
}

// ---------------- 1) avgpool(3,2,1) + channel mean/max (px-split) ----------
__global__ void pool_part_kernel(const float* __restrict__ x) {
    __shared__ float srow[7][DIM];
    int quarter = blockIdx.x, py = blockIdx.y, b = blockIdx.z;
    int c = threadIdx.x, lane = c & 31, w = c >> 5;
    int px0 = quarter * 7;
    const float* base = x + (size_t)b * IMG * IMG * DIM + c;
    int rm = 2 * py - 1, r0 = 2 * py, rp = 2 * py + 1;
    bool vm = rm >= 0;

    float cs[15];
#pragma unroll
    for (int i = 0; i < 15; i++) {
        int ix = 2 * px0 - 1 + i;
        if ((unsigned)ix < IMG) {
            float v = base[(size_t)(r0 * IMG + ix) * DIM] + base[(size_t)(rp * IMG + ix) * DIM];
            if (vm) v += base[(size_t)(rm * IMG + ix) * DIM];
            cs[i] = v;
        } else cs[i] = 0.f;
    }
    float* outp = g_xpool + ((size_t)b * NPOS + py * PP + px0) * DIM + c;
#pragma unroll
    for (int i = 0; i < 7; i++) {
        float pool = (cs[2 * i] + cs[2 * i + 1] + cs[2 * i + 2]) * (1.f / 9.f);
        outp[(size_t)i * DIM] = pool;
        srow[i][c] = pool;
    }
    __syncthreads();
    if (w < 7) {
        float s = 0.f, m = -1e30f;
#pragma unroll
        for (int k = 0; k < 8; k++) {
            float v = srow[w][lane + 32 * k];
            s += v; m = fmaxf(m, v);
        }
#pragma unroll
        for (int o = 16; o > 0; o >>= 1) {
            s += __shfl_down_sync(0xffffffffu, s, o);
            m = fmaxf(m, __shfl_down_sync(0xffffffffu, m, o));
        }
        if (lane == 0) {
            g_attn2[((size_t)b * NPOS + py * PP + px0 + w) * 2 + 0] = s * (1.f / DIM);
            g_attn2[((size_t)b * NPOS + py * PP + px0 + w) * 2 + 1] = m;
        }
    }
}

// ---------------- 2) q/k 3x3 convs (8 positions per block) -----------------
__global__ void qk_conv_kernel(const float* __restrict__ qw, const float* __restrict__ qb,
                               const float* __restrict__ kw, const float* __restrict__ kb) {
    int t = threadIdx.x;
    int p = blockIdx.x * 8 + (t >> 5), b = blockIdx.y;
    int tt = t & 31;
    int sel = tt >> 4, och = tt & 15;
    const float* w = sel ? kw : qw;
    const float* bi = sel ? kb : qb;
    float* outp = sel ? g_k : g_q;
    int py = p / PP, px = p % PP;
    float acc = bi[och];
#pragma unroll
    for (int dy = 0; dy < 3; dy++) {
        int iy = py - 1 + dy;
        if ((unsigned)iy >= PP) continue;
#pragma unroll
        for (int dx = 0; dx < 3; dx++) {
            int ix = px - 1 + dx;
            if ((unsigned)ix >= PP) continue;
            const float* a2 = &g_attn2[((size_t)b * NPOS + iy * PP + ix) * 2];
            acc += w[((och * 2 + 0) * 3 + dy) * 3 + dx] * a2[0]
                 + w[((och * 2 + 1) * 3 + dy) * 3 + dx] * a2[1];
        }
    }
    int h = och >> 1, comp = och & 1;
    outp[(((size_t)b * HEADS + h) * NPOS + p) * 2 + comp] = acc;
}

// ---------------- 3) depthwise 3x3 + BN + GELU (px-split, 2ch/thread) ------
// block = (quarter, py, b), 128 threads; thread owns channels 2c, 2c+1.
// 27 float2 loads: same bytes as before, half the instructions/address math.
__global__ void dw_part_kernel(const float* __restrict__ dww, const float* __restrict__ dwb,
                               const float* __restrict__ gamma, const float* __restrict__ beta,
                               const float* __restrict__ mean, const float* __restrict__ var) {
    int quarter = blockIdx.x, py = blockIdx.y, b = blockIdx.z, c2 = threadIdx.x;
    int c = 2 * c2;
    int px0 = quarter * 7;
    float2 wgt[9];
#pragma unroll
    for (int k = 0; k < 9; k++)
        wgt[k] = make_float2(dww[c * 9 + k], dww[(c + 1) * 9 + k]);
    float2 bias = *(const float2*)&dwb[c];
    float2 gmm = *(const float2*)&gamma[c];
    float2 vr2 = *(const float2*)&var[c];
    float2 sc = make_float2(gmm.x * rsqrtf(vr2.x + 1e-5f), gmm.y * rsqrtf(vr2.y + 1e-5f));
    float2 bm = *(const float2*)&mean[c];
    float2 bb = *(const float2*)&beta[c];

    const float* basep = g_xpool + (size_t)b * NPOS * DIM + c;
    float2 vin[3][9];
#pragma unroll
    for (int r = 0; r < 3; r++) {
        int row = py - 1 + r;
        bool vr = (unsigned)row < PP;
#pragma unroll
        for (int cc = 0; cc < 9; cc++) {
            int col = px0 - 1 + cc;
            vin[r][cc] = (vr && (unsigned)col < PP)
                       ? *(const float2*)&basep[(size_t)(row * PP + col) * DIM]
                       : make_float2(0.f, 0.f);
        }
    }
    __half* outp = g_vmid_h + ((size_t)b * NPOS + py * PP + px0) * DIM + c;
#pragma unroll
    for (int i = 0; i < 7; i++) {
        float ax = bias.x, ay = bias.y;
#pragma unroll
        for (int r = 0; r < 3; r++)
#pragma unroll
            for (int d = 0; d < 3; d++) {
                ax = fmaf(wgt[r * 3 + d].x, vin[r][i + d].x, ax);
                ay = fmaf(wgt[r * 3 + d].y, vin[r][i + d].y, ay);
            }
        ax = (ax - bm.x) * sc.x + bb.x;
        ay = (ay - bm.y) * sc.y + bb.y;
        ax = 0.5f * ax * (1.f + erff(ax * 0.70710678118654752f));
        ay = 0.5f * ay * (1.f + erff(ay * 0.70710678118654752f));
        *(uint32_t*)&outp[(size_t)i * DIM] = pack_h2(ax, ay);
    }
}

// ---------------- fp16 mma GEMM: C[M,N] = A[M,K]*B[N,K]^T + bias -----------
// 128x128 block tile, 256 threads (8 warps 4x2; warp tile 32x64), K-chunk 32.
__global__ __launch_bounds__(256) void gemm_h_kernel(
        const __half* __restrict__ A, const __half* __restrict__ B,
        const float* __restrict__ bias, void* __restrict__ Cv,
        int M, int N, int K, int out_half) {
    __shared__ uint2 As2[2][2][128][4];
    __shared__ uint2 Bs2[2][2][128][4];
    int tid = threadIdx.x;
    int lane = tid & 31, w = tid >> 5, g = lane >> 2, tig = lane & 3;
    int wm = w >> 1, wn = w & 1;
    int m0 = blockIdx.y * 128, n0 = blockIdx.x * 128;
    float c[2][8][4] = {};

    int nchunks = K >> 5;
    int arow[2], aq[2];
#pragma unroll
    for (int i = 0; i < 2; i++) { int s = tid + i * 256; arow[i] = s >> 2; aq[i] = s & 3; }
    uint4 ra[2], rb[2];

#pragma unroll
    for (int i = 0; i < 2; i++) {
        ra[i] = *(const uint4*)&A[(size_t)(m0 + arow[i]) * K + aq[i] * 8];
        rb[i] = *(const uint4*)&B[(size_t)(n0 + arow[i]) * K + aq[i] * 8];
    }

#pragma unroll
    for (int i = 0; i < 2; i++) {
        uint32_t* pa = (uint32_t*)&As2[0][aq[i] >> 1][arow[i]][0] + (aq[i] & 1);
        pa[0] = ra[i].x; pa[2] = ra[i].y; pa[4] = ra[i].z; pa[6] = ra[i].w;
        uint32_t* pb = (uint32_t*)&Bs2[0][aq[i] >> 1][arow[i]][0] + (aq[i] & 1);
        pb[0] = rb[i].x; pb[2] = rb[i].y; pb[4] = rb[i].z; pb[6] = rb[i].w;
    }
    __syncthreads();

    for (int kc = 0; kc < nchunks; kc++) {
        int cur = kc & 1;
        if (kc + 1 < nchunks) {
            int ko = (kc + 1) * 32;
#pragma unroll
            for (int i = 0; i < 2; i++) {
                ra[i] = *(const uint4*)&A[(size_t)(m0 + arow[i]) * K + ko + aq[i] * 8];
                rb[i] = *(const uint4*)&B[(size_t)(n0 + arow[i]) * K + ko + aq[i] * 8];
            }
        }
#pragma unroll
        for (int kg = 0; kg < 2; kg++) {
            uint2 a00 = As2[cur][kg][wm * 32 + g][tig];
            uint2 a08 = As2[cur][kg][wm * 32 + 8 + g][tig];
            uint2 a16 = As2[cur][kg][wm * 32 + 16 + g][tig];
            uint2 a24 = As2[cur][kg][wm * 32 + 24 + g][tig];
#pragma unroll
            for (int nt = 0; nt < 8; nt++) {
                uint2 bb = Bs2[cur][kg][wn * 64 + nt * 8 + g][tig];
                mma_h(c[0][nt], a00.x, a08.x, a00.y, a08.y, bb.x, bb.y);
                mma_h(c[1][nt], a16.x, a24.x, a16.y, a24.y, bb.x, bb.y);
            }
        }
        if (kc + 1 < nchunks) {
            int nxt = cur ^ 1;
#pragma unroll
            for (int i = 0; i < 2; i++) {
                uint32_t* pa = (uint32_t*)&As2[nxt][aq[i] >> 1][arow[i]][0] + (aq[i] & 1);
                pa[0] = ra[i].x; pa[2] = ra[i].y; pa[4] = ra[i].z; pa[6] = ra[i].w;
                uint32_t* pb = (uint32_t*)&Bs2[nxt][aq[i] >> 1][arow[i]][0] + (aq[i] & 1);
                pb[0] = rb[i].x; pb[2] = rb[i].y; pb[4] = rb[i].z; pb[6] = rb[i].w;
            }
            __syncthreads();
        }
    }
#pragma unroll
    for (int mt = 0; mt < 2; mt++) {
        int r = m0 + wm * 32 + mt * 16 + g;
#pragma unroll
        for (int nt = 0; nt < 8; nt++) {
            int n = n0 + wn * 64 + nt * 8 + 2 * tig;
            float bx = bias[n], by = bias[n + 1];
            float o0 = c[mt][nt][0] + bx, o1 = c[mt][nt][1] + by;
            float o2 = c[mt][nt][2] + bx, o3 = c[mt][nt][3] + by;
            if (out_half) {
                __half* C = (__half*)Cv;
                *(uint32_t*)&C[(size_t)r * N + n] = pack_h2(o0, o1);
                *(uint32_t*)&C[(size_t)(r + 8) * N + n] = pack_h2(o2, o3);
            } else {
                float* C = (float*)Cv;
                *(float2*)&C[(size_t)r * N + n] = make_float2(o0, o1);
                *(float2*)&C[(size_t)(r + 8) * N + n] = make_float2(o2, o3);
            }
        }
    }
}

// ---------------- 5) attention per (b,h): legacy fp16 mma -------------------
// 25 warps, 1 q-tile per sweep; fp16x2 MUFU exp; row-sums via ONES-mma.
__global__ __launch_bounds__(800, 1) void attn_h_kernel() {
    extern __shared__ char smc[];
    uint2* Vp = (uint2*)smc;                         // [49][64][4] : 100352 B
    float2* kxy = (float2*)(smc + 49 * 64 * 4 * 8);  // 784 float2 : 6272 B
    int h = blockIdx.x, b = blockIdx.y;
    int tid = threadIdx.x, lane = tid & 31, w = tid >> 5;
    int g = lane >> 2, tig = lane & 3;
    const uint32_t ONES = 0x3C003C00u;               // (1.0h, 1.0h)

    const __half* vsrc = g_v_h + (size_t)b * NPOS * INNER + h * DH;
    for (int i = tid; i < 392 * 32; i += 800) {
        int jp = i >> 5, n2 = (i & 31) * 2;
        uint32_t a = *(const uint32_t*)&vsrc[(size_t)(2 * jp) * INNER + n2];
        uint32_t bu = *(const uint32_t*)&vsrc[(size_t)(2 * jp + 1) * INNER + n2];
        uint32_t o0 = __byte_perm(a, bu, 0x5410);
        uint32_t o1 = __byte_perm(a, bu, 0x7632);
        int jg = jp >> 3, lp = jp & 7;
        int t4 = lp & 3, hf = lp >> 2;
        ((uint32_t*)&Vp[(jg * 64 + n2) * 4 + t4])[hf] = o0;
        ((uint32_t*)&Vp[(jg * 64 + n2 + 1) * 4 + t4])[hf] = o1;
    }
    const float* ksrc = g_k + ((size_t)b * HEADS + h) * NPOS * 2;
    const float KSC = 0.125f * 1.4426950408889634f;  // scale * log2(e)
    for (int i = tid; i < NPOS; i += 800) {
        float2 kv = ((const float2*)ksrc)[i];
        kxy[i] = make_float2(kv.x * KSC, kv.y * KSC);
    }
    __syncthreads();

    const float2* qsrc = (const float2*)(g_q + ((size_t)b * HEADS + h) * NPOS * 2);
    __half* odst = g_ao_h + (size_t)b * NPOS * INNER + h * DH;

    for (int t = w; t < 49; t += 25) {
        int r0 = t * 16 + g, r1 = r0 + 8;
        float2 q0 = qsrc[r0], q1 = qsrc[r1];
        float c[8][4] = {};
        float cl[4] = {};
        for (int jg = 0; jg < 49; jg++) {
            float4 kk0 = *(const float4*)&kxy[jg * 16 + 2 * tig];
            float4 kk1 = *(const float4*)&kxy[jg * 16 + 2 * tig + 8];
            uint32_t a0 = exp2_h2(fmaf(q0.x, kk0.x, q0.y * kk0.y),
                                  fmaf(q0.x, kk0.z, q0.y * kk0.w));
            uint32_t a1 = exp2_h2(fmaf(q1.x, kk0.x, q1.y * kk0.y),
                                  fmaf(q1.x, kk0.z, q1.y * kk0.w));
            uint32_t a2 = exp2_h2(fmaf(q0.x, kk1.x, q0.y * kk1.y),
                                  fmaf(q0.x, kk1.z, q0.y * kk1.w));
            uint32_t a3 = exp2_h2(fmaf(q1.x, kk1.x, q1.y * kk1.y),
                                  fmaf(q1.x, kk1.z, q1.y * kk1.w));
            const uint2* vrow = &Vp[(jg * 64) * 4 + tig];
#pragma unroll
            for (int nt = 0; nt < 8; nt++) {
                uint2 bb = vrow[(nt * 8 + g) * 4];
                mma_h(c[nt], a0, a1, a2, a3, bb.x, bb.y);
            }
            mma_h(cl, a0, a1, a2, a3, ONES, ONES);
        }
        float i0 = 1.f / cl[0], i1 = 1.f / cl[2];
#pragma unroll
        for (int nt = 0; nt < 8; nt++) {
            int n = nt * 8 + 2 * tig;
            *(uint32_t*)&odst[(size_t)r0 * INNER + n] = pack_h2(c[nt][0] * i0, c[nt][1] * i0);
            *(uint32_t*)&odst[(size_t)r1 * INNER + n] = pack_h2(c[nt][2] * i1, c[nt][3] * i1);
        }
    }
}

// ---------------- 7) bicubic x2 upsample, paired output rows ---------------
__global__ void upsample3_kernel(float* __restrict__ out) {
    extern __shared__ float tmp[];   // [2][PP][DIM] dynamic (57344 B)
    float* tmp0 = tmp;
    float* tmp1 = tmp + PP * DIM;
    int m = blockIdx.x, b = blockIdx.y, c = threadIdx.x;
    int ry[5];
#pragma unroll
    for (int r = 0; r < 5; r++) ry[r] = min(max(m - 2 + r, 0), PP - 1);
    const float* basep = g_y28 + (size_t)b * NPOS * DIM + c;
#pragma unroll 7
    for (int ix = 0; ix < PP; ix++) {
        float v0 = basep[(size_t)(ry[0] * PP + ix) * DIM];
        float v1 = basep[(size_t)(ry[1] * PP + ix) * DIM];
        float v2 = basep[(size_t)(ry[2] * PP + ix) * DIM];
        float v3 = basep[(size_t)(ry[3] * PP + ix) * DIM];
        float v4 = basep[(size_t)(ry[4] * PP + ix) * DIM];
        tmp0[ix * DIM + c] = c_W75[0] * v0 + c_W75[1] * v1 + c_W75[2] * v2 + c_W75[3] * v3;
        tmp1[ix * DIM + c] = c_W25[0] * v1 + c_W25[1] * v2 + c_W25[2] * v3 + c_W25[3] * v4;
    }
    __syncthreads();
    float* orow0 = out + ((size_t)b * IMG * IMG + (2 * m) * IMG) * DIM + c;
    float* orow1 = orow0 + (size_t)IMG * DIM;
#pragma unroll 4
    for (int ox = 0; ox < IMG; ox++) {
        int ix0; const float* wx;
        if (ox & 1) { ix0 = (ox - 1) >> 1; wx = c_W25; }
        else        { ix0 = (ox >> 1) - 1; wx = c_W75; }
        int sx0 = min(max(ix0 - 1, 0), PP - 1);
        int sx1 = min(max(ix0 + 0, 0), PP - 1);
        int sx2 = min(max(ix0 + 1, 0), PP - 1);
        int sx3 = min(max(ix0 + 2, 0), PP - 1);
        float a0 = wx[0] * tmp0[sx0 * DIM + c] + wx[1] * tmp0[sx1 * DIM + c]
                 + wx[2] * tmp0[sx2 * DIM + c] + wx[3] * tmp0[sx3 * DIM + c];
        float a1 = wx[0] * tmp1[sx0 * DIM + c] + wx[1] * tmp1[sx1 * DIM + c]
                 + wx[2] * tmp1[sx2 * DIM + c] + wx[3] * tmp1[sx3 * DIM + c];
        orow0[(size_t)ox * DIM] = a0;
        orow1[(size_t)ox * DIM] = a1;
    }
}

// ---------------- launch ---------------------------------------------------
extern "C" void kernel_launch(void* const* d_in, const int* in_sizes, int n_in,
                              void* d_out, int out_size) {
    const float* x     = (const float*)d_in[0];
    const float* q_w   = (const float*)d_in[1];
    const float* q_b   = (const float*)d_in[2];
    const float* k_w   = (const float*)d_in[3];
    const float* k_b   = (const float*)d_in[4];
    const float* dw_w  = (const float*)d_in[5];
    const float* dw_b  = (const float*)d_in[6];
    const float* bn_g  = (const float*)d_in[7];
    const float* bn_b  = (const float*)d_in[8];
    const float* bn_m  = (const float*)d_in[9];
    const float* bn_v  = (const float*)d_in[10];
    const float* pw_w  = (const float*)d_in[11];
    const float* pw_b  = (const float*)d_in[12];
    const float* out_w = (const float*)d_in[13];
    const float* out_b = (const float*)d_in[14];
    float* out = (float*)d_out;

    const int ATTN_SMEM = 49 * 64 * 4 * 8 + NPOS * 8;          // 106624
    const int UPS_SMEM  = 2 * PP * DIM * (int)sizeof(float);   // 57344
    cudaFuncSetAttribute(attn_h_kernel, cudaFuncAttributeMaxDynamicSharedMemorySize, ATTN_SMEM);
    cudaFuncSetAttribute(upsample3_kernel, cudaFuncAttributeMaxDynamicSharedMemorySize, UPS_SMEM);

    void *p_vmid, *p_v, *p_ao, *p_y28, *p_pww, *p_oww;
    cudaGetSymbolAddress(&p_vmid, g_vmid_h);
    cudaGetSymbolAddress(&p_v, g_v_h);
    cudaGetSymbolAddress(&p_ao, g_ao_h);
    cudaGetSymbolAddress(&p_y28, g_y28);
    cudaGetSymbolAddress(&p_pww, g_pww_h);
    cudaGetSymbolAddress(&p_oww, g_oww_h);

    round_weights_kernel<<<(INNER * DIM + 255) / 256, 256>>>(pw_w, out_w);
    pool_part_kernel<<<dim3(4, PP, BATCH), 256>>>(x);
    qk_conv_kernel<<<dim3(NPOS / 8, BATCH), 256>>>(q_w, q_b, k_w, k_b);
    dw_part_kernel<<<dim3(4, PP, BATCH), 128>>>(dw_w, dw_b, bn_g, bn_b, bn_m, bn_v);
    // pointwise conv: [12544,256] x [512,256]^T -> fp16 [12544,512]
    gemm_h_kernel<<<dim3(INNER / 128, (BATCH * NPOS) / 128), 256>>>(
        (const __half*)p_vmid, (const __half*)p_pww, pw_b, p_v,
        BATCH * NPOS, INNER, DIM, 1);
    attn_h_kernel<<<dim3(HEADS, BATCH), 800, ATTN_SMEM>>>();
    // output projection: [12544,512] x [256,512]^T -> fp32 [12544,256]
    gemm_h_kernel<<<dim3(DIM / 128, (BATCH * NPOS) / 128), 256>>>(
        (const __half*)p_ao, (const __half*)p_oww, out_b, p_y28,
        BATCH * NPOS, DIM, INNER, 0);
    upsample3_kernel<<<dim3(PP, BATCH), 256, UPS_SMEM>>>(out);
}